// round 3
// baseline (speedup 1.0000x reference)
#include <cuda_runtime.h>
#include <math.h>

#define B 8
#define T 2048
#define C 1024
#define H 128
#define BT (B * T)

// Scratch for projected Q/K/V: 3 x 8MB (device globals, no allocation)
__device__ float g_Q[BT * H];
__device__ float g_K[BT * H];
__device__ float g_V[BT * H];

// ---------------------------------------------------------------------------
// Projection: out[m][n] = sum_k x[m][k] * W[k][n],  M=BT, K=C, N=H
// Grid: (BT/64, 3)  blockIdx.y selects Wq/Wk/Wv -> g_Q/g_K/g_V
// Block: 256 threads, 64x128 output tile, K-chunks of 32, 4x8 micro-tile.
// ---------------------------------------------------------------------------
__global__ __launch_bounds__(256) void proj_kernel(
    const float* __restrict__ x,
    const float* __restrict__ Wq,
    const float* __restrict__ Wk,
    const float* __restrict__ Wv)
{
    __shared__ float xs[64][33];    // padded: conflict-free row reads
    __shared__ float ws[32][128];

    const float* W  = (blockIdx.y == 0) ? Wq : (blockIdx.y == 1) ? Wk : Wv;
    float*       out = (blockIdx.y == 0) ? g_Q : (blockIdx.y == 1) ? g_K : g_V;

    const int m0  = blockIdx.x * 64;
    const int tid = threadIdx.x;
    const int ty  = tid >> 4;      // 0..15 -> q-row group
    const int tx  = tid & 15;      // 0..15 -> col group

    float acc[4][8];
    #pragma unroll
    for (int i = 0; i < 4; i++)
        #pragma unroll
        for (int j = 0; j < 8; j++) acc[i][j] = 0.0f;

    for (int k0 = 0; k0 < C; k0 += 32) {
        // load x tile 64x32
        #pragma unroll
        for (int i = tid; i < 64 * 32; i += 256) {
            int r = i >> 5, c = i & 31;
            xs[r][c] = x[(size_t)(m0 + r) * C + k0 + c];
        }
        // load W tile 32x128
        #pragma unroll
        for (int i = tid; i < 32 * 128; i += 256) {
            int r = i >> 7, c = i & 127;
            ws[r][c] = W[(size_t)(k0 + r) * H + c];
        }
        __syncthreads();

        #pragma unroll
        for (int kk = 0; kk < 32; kk++) {
            float a[4], bb[8];
            #pragma unroll
            for (int i = 0; i < 4; i++) a[i] = xs[i * 16 + ty][kk];
            #pragma unroll
            for (int j = 0; j < 8; j++) bb[j] = ws[kk][j * 16 + tx];
            #pragma unroll
            for (int i = 0; i < 4; i++)
                #pragma unroll
                for (int j = 0; j < 8; j++) acc[i][j] = fmaf(a[i], bb[j], acc[i][j]);
        }
        __syncthreads();
    }

    #pragma unroll
    for (int i = 0; i < 4; i++) {
        int m = m0 + i * 16 + ty;
        #pragma unroll
        for (int j = 0; j < 8; j++) {
            out[(size_t)m * H + j * 16 + tx] = acc[i][j];
        }
    }
}

// ---------------------------------------------------------------------------
// Flash attention (fp32, causal): one CTA per (batch, 64-query tile).
// 256 threads. S = Q K^T (4x4 micro-tile), online softmax (shfl over 16-lane
// row groups), P staged in smem, O += P V (4x8 micro-tile).
// ---------------------------------------------------------------------------
#define QSTRIDE 129
#define KSTRIDE 129
#define VSTRIDE 128
#define PSTRIDE 65

__global__ __launch_bounds__(256) void attn_kernel(float* __restrict__ out)
{
    extern __shared__ float sm[];
    float* Qs = sm;                       // 64 * 129
    float* Ks = Qs + 64 * QSTRIDE;        // 64 * 129
    float* Vs = Ks + 64 * KSTRIDE;        // 64 * 128
    float* Ps = Vs + 64 * VSTRIDE;        // 64 * 65

    const int b   = blockIdx.y;
    const int q0  = blockIdx.x * 64;
    const int tid = threadIdx.x;
    const int ty  = tid >> 4;
    const int tx  = tid & 15;

    const float* Qg = g_Q + (size_t)b * T * H;
    const float* Kg = g_K + (size_t)b * T * H;
    const float* Vg = g_V + (size_t)b * T * H;

    // Load Q tile once
    #pragma unroll
    for (int i = tid; i < 64 * H; i += 256) {
        int r = i >> 7, c = i & 127;
        Qs[r * QSTRIDE + c] = Qg[(size_t)(q0 + r) * H + c];
    }

    float m_i[4], l_i[4], o[4][8];
    #pragma unroll
    for (int i = 0; i < 4; i++) {
        m_i[i] = -INFINITY;
        l_i[i] = 0.0f;
        #pragma unroll
        for (int j = 0; j < 8; j++) o[i][j] = 0.0f;
    }

    const float scale = 0.08838834764831845f;  // 1/sqrt(128)
    const int ntiles = q0 / 64 + 1;            // causal: skip tiles above diag

    for (int t = 0; t < ntiles; t++) {
        const int s0 = t * 64;
        __syncthreads();   // previous iteration's consumers done before overwrite
        #pragma unroll
        for (int i = tid; i < 64 * H; i += 256) {
            int r = i >> 7, c = i & 127;
            Ks[r * KSTRIDE + c] = Kg[(size_t)(s0 + r) * H + c];
            Vs[r * VSTRIDE + c] = Vg[(size_t)(s0 + r) * H + c];
        }
        __syncthreads();

        // S = Q K^T  (4x4 per thread)
        float s_acc[4][4];
        #pragma unroll
        for (int i = 0; i < 4; i++)
            #pragma unroll
            for (int j = 0; j < 4; j++) s_acc[i][j] = 0.0f;

        #pragma unroll 4
        for (int h = 0; h < H; h++) {
            float a[4], bb[4];
            #pragma unroll
            for (int i = 0; i < 4; i++) a[i] = Qs[(i * 16 + ty) * QSTRIDE + h];
            #pragma unroll
            for (int j = 0; j < 4; j++) bb[j] = Ks[(j * 16 + tx) * KSTRIDE + h];
            #pragma unroll
            for (int i = 0; i < 4; i++)
                #pragma unroll
                for (int j = 0; j < 4; j++)
                    s_acc[i][j] = fmaf(a[i], bb[j], s_acc[i][j]);
        }

        const bool diag = (s0 == q0);

        // scale + causal mask + online softmax
        #pragma unroll
        for (int i = 0; i < 4; i++) {
            const int qi = i * 16 + ty;
            float z[4];
            #pragma unroll
            for (int j = 0; j < 4; j++) {
                float v = s_acc[i][j] * scale;
                if (diag && (j * 16 + tx) > qi) v = -INFINITY;
                z[j] = v;
            }
            float mt = fmaxf(fmaxf(z[0], z[1]), fmaxf(z[2], z[3]));
            #pragma unroll
            for (int off = 8; off >= 1; off >>= 1)
                mt = fmaxf(mt, __shfl_xor_sync(0xffffffffu, mt, off, 16));

            const float mnew  = fmaxf(m_i[i], mt);
            const float alpha = __expf(m_i[i] - mnew);

            float rowsum = 0.0f;
            float p[4];
            #pragma unroll
            for (int j = 0; j < 4; j++) {
                p[j] = __expf(z[j] - mnew);
                rowsum += p[j];
            }
            #pragma unroll
            for (int off = 8; off >= 1; off >>= 1)
                rowsum += __shfl_xor_sync(0xffffffffu, rowsum, off, 16);

            l_i[i] = l_i[i] * alpha + rowsum;
            m_i[i] = mnew;
            #pragma unroll
            for (int j = 0; j < 8; j++) o[i][j] *= alpha;
            #pragma unroll
            for (int j = 0; j < 4; j++)
                Ps[qi * PSTRIDE + j * 16 + tx] = p[j];
        }
        __syncthreads();

        // O += P @ V  (4x8 per thread)
        #pragma unroll 4
        for (int kk = 0; kk < 64; kk++) {
            float pv[4], vv[8];
            #pragma unroll
            for (int i = 0; i < 4; i++) pv[i] = Ps[(i * 16 + ty) * PSTRIDE + kk];
            #pragma unroll
            for (int j = 0; j < 8; j++) vv[j] = Vs[kk * VSTRIDE + j * 16 + tx];
            #pragma unroll
            for (int i = 0; i < 4; i++)
                #pragma unroll
                for (int j = 0; j < 8; j++)
                    o[i][j] = fmaf(pv[i], vv[j], o[i][j]);
        }
    }

    // Normalize and write
    float* Og = out + (size_t)b * T * H;
    #pragma unroll
    for (int i = 0; i < 4; i++) {
        const float inv_l = 1.0f / l_i[i];
        const int m = q0 + i * 16 + ty;
        #pragma unroll
        for (int j = 0; j < 8; j++)
            Og[(size_t)m * H + j * 16 + tx] = o[i][j] * inv_l;
    }
}

extern "C" void kernel_launch(void* const* d_in, const int* in_sizes, int n_in,
                              void* d_out, int out_size)
{
    const float* x  = (const float*)d_in[0];
    const float* Wq = (const float*)d_in[1];
    const float* Wk = (const float*)d_in[2];
    const float* Wv = (const float*)d_in[3];
    float* out = (float*)d_out;

    // 1) QKV projections
    proj_kernel<<<dim3(BT / 64, 3), 256>>>(x, Wq, Wk, Wv);

    // 2) Flash attention
    const int smem_bytes = (64 * (QSTRIDE + KSTRIDE + VSTRIDE + PSTRIDE)) * sizeof(float);
    cudaFuncSetAttribute(attn_kernel, cudaFuncAttributeMaxDynamicSharedMemorySize, smem_bytes);
    attn_kernel<<<dim3(T / 64, B), 256, smem_bytes>>>(out);
}

// round 6
// speedup vs baseline: 1.7189x; 1.7189x over previous
#include <cuda_runtime.h>
#include <cuda_bf16.h>
#include <cstdint>
#include <math.h>

#define Bn 8
#define Tn 2048
#define Cn 1024
#define Hn 128
#define BT (Bn * Tn)

// bf16 hi/lo scratch (device globals, no allocation)
__device__ __nv_bfloat16 g_Qh[BT * Hn], g_Ql[BT * Hn];
__device__ __nv_bfloat16 g_Kh[BT * Hn], g_Kl[BT * Hn];
__device__ __nv_bfloat16 g_Vh[BT * Hn], g_Vl[BT * Hn];
__device__ __nv_bfloat16 g_Wh[3 * Hn * Cn], g_Wl[3 * Hn * Cn];  // [o][n][k]

// ---------------- helpers ----------------
#define SWZ(x) ((x) ^ (((x) >> 3) & 0x70))

__device__ __forceinline__ uint32_t smem_u32(const void* p) {
    uint32_t a;
    asm("{ .reg .u64 t; cvta.to.shared.u64 t, %1; cvt.u32.u64 %0, t; }" : "=r"(a) : "l"(p));
    return a;
}
// pack two fp32 -> bf16x2 (lo = first arg, hi = second)
__device__ __forceinline__ uint32_t pack2(float lo, float hi) {
    uint32_t r;
    asm("cvt.rn.bf16x2.f32 %0, %1, %2;" : "=r"(r) : "f"(hi), "f"(lo));
    return r;
}
// split (a,b) fp32 pair into bf16 hi word + bf16 lo word
__device__ __forceinline__ void split2(float a, float b, uint32_t& h, uint32_t& l) {
    float ah = __bfloat162float(__float2bfloat16(a));
    float bh = __bfloat162float(__float2bfloat16(b));
    h = pack2(ah, bh);
    l = pack2(a - ah, b - bh);
}
__device__ __forceinline__ void ldsm4(uint32_t* r, uint32_t addr) {
    asm volatile("ldmatrix.sync.aligned.m8n8.x4.shared.b16 {%0,%1,%2,%3}, [%4];"
                 : "=r"(r[0]), "=r"(r[1]), "=r"(r[2]), "=r"(r[3]) : "r"(addr));
}
__device__ __forceinline__ void mma_bf16(float* d, const uint32_t* a, uint32_t b0, uint32_t b1) {
    asm volatile("mma.sync.aligned.m16n8k16.row.col.f32.bf16.bf16.f32 "
                 "{%0,%1,%2,%3}, {%4,%5,%6,%7}, {%8,%9}, {%0,%1,%2,%3};"
                 : "+f"(d[0]), "+f"(d[1]), "+f"(d[2]), "+f"(d[3])
                 : "r"(a[0]), "r"(a[1]), "r"(a[2]), "r"(a[3]), "r"(b0), "r"(b1));
}
// ldmatrix address for A-operand 16x16 tile at (r0, bytecol), 128B-pitch tile
__device__ __forceinline__ uint32_t aAddr(uint32_t base, int r0, int bc, int lane) {
    int r = r0 + (lane & 15);
    int c = bc + ((lane >> 4) << 4);
    return base + SWZ((uint32_t)(r * 128 + c));
}
// ldmatrix address for B-operand x4 (two n8 tiles) at (n0, bytecol)
__device__ __forceinline__ uint32_t bAddr(uint32_t base, int n0, int bc, int lane) {
    int r = n0 + (lane & 7) + ((lane >> 4) << 3);
    int c = bc + (((lane >> 3) & 1) << 4);
    return base + SWZ((uint32_t)(r * 128 + c));
}

// ============================================================================
// convW: W[o][k][n] fp32 -> g_Wh/g_Wl [o][n][k] bf16 hi/lo
// ============================================================================
__global__ void convW(const float* __restrict__ Wq, const float* __restrict__ Wk,
                      const float* __restrict__ Wv) {
    int idx = blockIdx.x * 256 + threadIdx.x;     // 3*1024*128 total
    int o = idx >> 17, rem = idx & 131071;
    int k = rem >> 7, n = rem & 127;
    const float* W = o == 0 ? Wq : o == 1 ? Wk : Wv;
    float f = W[(size_t)k * Hn + n];
    __nv_bfloat16 h = __float2bfloat16(f);
    size_t dst = ((size_t)o * Hn + n) * Cn + k;
    g_Wh[dst] = h;
    g_Wl[dst] = __float2bfloat16(f - __bfloat162float(h));
}

// ============================================================================
// Projection: 384 thr (12 warps = 4 m-blocks x 3 outputs), CTA = 128 rows.
// smem: XHI 0 (16K), XLO 16384, WHI 32768 (48K), WLO 81920.  K-chunks of 64.
// ============================================================================
#define PJ_SMEM (131072 + 128)

__global__ __launch_bounds__(384, 1) void proj_mma(const float* __restrict__ x) {
    extern __shared__ char smraw[];
    char* sm = (char*)(((uintptr_t)smraw + 127) & ~(uintptr_t)127);
    const uint32_t sb = smem_u32(sm);
    const int tid = threadIdx.x, lane = tid & 31, wid = tid >> 5;
    const int mw = wid & 3, ow = wid >> 2;    // m-block, output index
    const int m0 = blockIdx.x * 128;

    float d[2][16][4];
    #pragma unroll
    for (int i = 0; i < 2; i++)
        #pragma unroll
        for (int j = 0; j < 16; j++)
            #pragma unroll
            for (int e = 0; e < 4; e++) d[i][j][e] = 0.0f;

    for (int kc = 0; kc < 16; kc++) {
        if (kc > 0) __syncthreads();   // mma of prev chunk done before restage
        // stage x chunk (threads 0-255): row = tid/2, 32 k each
        if (tid < 256) {
            int row = tid >> 1, kq = (tid & 1) * 32;
            const float* xp = x + (size_t)(m0 + row) * Cn + kc * 64 + kq;
            #pragma unroll
            for (int g = 0; g < 4; g++) {
                float4 v0 = *(const float4*)(xp + g * 8);
                float4 v1 = *(const float4*)(xp + g * 8 + 4);
                uint4 hi, lo;
                split2(v0.x, v0.y, hi.x, lo.x);
                split2(v0.z, v0.w, hi.y, lo.y);
                split2(v1.x, v1.y, hi.z, lo.z);
                split2(v1.z, v1.w, hi.w, lo.w);
                uint32_t off = (uint32_t)(row * 128 + kq * 2 + g * 16);
                *(uint4*)(sm + SWZ(off)) = hi;
                *(uint4*)(sm + 16384 + SWZ(off)) = lo;
            }
        }
        // stage W chunk (all 384 threads, 1 row each: 64 bf16 hi + lo)
        {
            const uint4* wh = (const uint4*)(g_Wh + (size_t)tid * Cn + kc * 64);
            const uint4* wl = (const uint4*)(g_Wl + (size_t)tid * Cn + kc * 64);
            #pragma unroll
            for (int i = 0; i < 8; i++) {
                uint32_t off = (uint32_t)(tid * 128 + i * 16);
                *(uint4*)(sm + 32768 + SWZ(off)) = wh[i];
                *(uint4*)(sm + 81920 + SWZ(off)) = wl[i];
            }
        }
        __syncthreads();

        #pragma unroll
        for (int pass = 0; pass < 3; pass++) {
            const uint32_t ab = sb + (pass == 1 ? 16384u : 0u);
            const uint32_t bb = sb + (pass == 2 ? 81920u : 32768u);
            #pragma unroll
            for (int kk = 0; kk < 4; kk++) {
                uint32_t a[2][4];
                #pragma unroll
                for (int mt = 0; mt < 2; mt++)
                    ldsm4(a[mt], aAddr(ab, mw * 32 + mt * 16, kk * 32, lane));
                #pragma unroll
                for (int p2 = 0; p2 < 8; p2++) {
                    uint32_t bf[4];
                    ldsm4(bf, bAddr(bb, ow * 128 + p2 * 16, kk * 32, lane));
                    #pragma unroll
                    for (int mt = 0; mt < 2; mt++) {
                        mma_bf16(d[mt][p2 * 2], a[mt], bf[0], bf[1]);
                        mma_bf16(d[mt][p2 * 2 + 1], a[mt], bf[2], bf[3]);
                    }
                }
            }
        }
    }

    // epilogue: split to bf16 hi/lo, write packed pairs
    __nv_bfloat16* oh = ow == 0 ? g_Qh : ow == 1 ? g_Kh : g_Vh;
    __nv_bfloat16* ol = ow == 0 ? g_Ql : ow == 1 ? g_Kl : g_Vl;
    #pragma unroll
    for (int mt = 0; mt < 2; mt++)
        #pragma unroll
        for (int h = 0; h < 2; h++) {
            int r = m0 + mw * 32 + mt * 16 + (lane >> 2) + h * 8;
            #pragma unroll
            for (int nt = 0; nt < 16; nt++) {
                int c = nt * 8 + (lane & 3) * 2;
                uint32_t hw, lw;
                split2(d[mt][nt][h * 2], d[mt][nt][h * 2 + 1], hw, lw);
                size_t byt = ((size_t)r * Hn + c) * 2;
                *(uint32_t*)((char*)oh + byt) = hw;
                *(uint32_t*)((char*)ol + byt) = lw;
            }
        }
}

// ============================================================================
// Attention: 256 thr (8 warps: 4 m-blocks x 2 n-blocks), CTA = 128 q-rows.
// 64-key tiles, max-free softmax, O in fp32 fragments across tiles.
// smem: Q hi 0/16384 (halves), Q lo 32768/49152, K hi 65536/73728,
//       K lo 81920/90112, Vt hi 98304, Vt lo 114688, P hi 131072, P lo 147456,
//       l[128] 163840.
// ============================================================================
#define AT_SMEM (163840 + 512 + 128)

__global__ __launch_bounds__(256, 1) void attn_mma(float* __restrict__ out) {
    extern __shared__ char smraw[];
    char* sm = (char*)(((uintptr_t)smraw + 127) & ~(uintptr_t)127);
    const uint32_t sb = smem_u32(sm);
    float* ls = (float*)(sm + 163840);
    const int tid = threadIdx.x, lane = tid & 31, wid = tid >> 5;
    const int mw = wid >> 1, nw = wid & 1;
    const int b = blockIdx.y, qi = blockIdx.x, q0 = qi * 128;

    if (tid < 128) ls[tid] = 0.0f;

    // stage Q (hi/lo, two h-halves)
    {
        int row = tid >> 1, half = tid & 1;
        size_t g = ((size_t)(b * Tn + q0 + row)) * Hn + half * 64;
        const uint4* qh = (const uint4*)(g_Qh + g);
        const uint4* ql = (const uint4*)(g_Ql + g);
        #pragma unroll
        for (int i = 0; i < 8; i++) {
            uint32_t off = SWZ((uint32_t)(row * 128 + i * 16));
            *(uint4*)(sm + half * 16384 + off) = qh[i];
            *(uint4*)(sm + 32768 + half * 16384 + off) = ql[i];
        }
    }

    float o[2][8][4];
    #pragma unroll
    for (int i = 0; i < 2; i++)
        #pragma unroll
        for (int j = 0; j < 8; j++)
            #pragma unroll
            for (int e = 0; e < 4; e++) o[i][j][e] = 0.0f;

    const float scale = 0.08838834764831845f;  // 1/sqrt(128)
    const int ntiles = 2 * qi + 2;

    for (int t = 0; t < ntiles; t++) {
        // stage K tile (row-major halves)
        {
            int row = tid >> 2, quad = tid & 3;
            size_t g = ((size_t)(b * Tn + t * 64 + row)) * Hn + quad * 32;
            const uint4* kh = (const uint4*)(g_Kh + g);
            const uint4* kl = (const uint4*)(g_Kl + g);
            int half = quad >> 1, hin = (quad & 1) * 64;
            #pragma unroll
            for (int i = 0; i < 4; i++) {
                uint32_t off = SWZ((uint32_t)(row * 128 + hin + i * 16));
                *(uint4*)(sm + 65536 + half * 8192 + off) = kh[i];
                *(uint4*)(sm + 81920 + half * 8192 + off) = kl[i];
            }
        }
        // stage V transposed: Vt[h][key]
        {
            int key = tid >> 2, quad = tid & 3;
            size_t g = ((size_t)(b * Tn + t * 64 + key)) * Hn + quad * 32;
            const uint4* vh4 = (const uint4*)(g_Vh + g);
            const uint4* vl4 = (const uint4*)(g_Vl + g);
            uint4 vh[4] = { vh4[0], vh4[1], vh4[2], vh4[3] };
            uint4 vl[4] = { vl4[0], vl4[1], vl4[2], vl4[3] };
            const uint16_t* hs = (const uint16_t*)vh;
            const uint16_t* lsrc = (const uint16_t*)vl;
            #pragma unroll
            for (int i = 0; i < 32; i++) {
                uint32_t off = SWZ((uint32_t)((quad * 32 + i) * 128 + key * 2));
                *(uint16_t*)(sm + 98304 + off) = hs[i];
                *(uint16_t*)(sm + 114688 + off) = lsrc[i];
            }
        }
        __syncthreads();

        // S = Q K^T
        float s[2][4][4];
        #pragma unroll
        for (int i = 0; i < 2; i++)
            #pragma unroll
            for (int j = 0; j < 4; j++)
                #pragma unroll
                for (int e = 0; e < 4; e++) s[i][j][e] = 0.0f;

        #pragma unroll
        for (int pass = 0; pass < 3; pass++) {
            uint32_t ab = sb + (pass == 1 ? 32768u : 0u);
            uint32_t bb = sb + (pass == 2 ? 81920u : 65536u);
            #pragma unroll
            for (int kk = 0; kk < 8; kk++) {
                uint32_t abase = ab + (uint32_t)(kk >> 2) * 16384u;
                uint32_t bbase = bb + (uint32_t)(kk >> 2) * 8192u;
                int bc = (kk & 3) * 32;
                uint32_t a[2][4];
                #pragma unroll
                for (int mt = 0; mt < 2; mt++)
                    ldsm4(a[mt], aAddr(abase, mw * 32 + mt * 16, bc, lane));
                #pragma unroll
                for (int p2 = 0; p2 < 2; p2++) {
                    uint32_t bf[4];
                    ldsm4(bf, bAddr(bbase, nw * 32 + p2 * 16, bc, lane));
                    #pragma unroll
                    for (int mt = 0; mt < 2; mt++) {
                        mma_bf16(s[mt][p2 * 2], a[mt], bf[0], bf[1]);
                        mma_bf16(s[mt][p2 * 2 + 1], a[mt], bf[2], bf[3]);
                    }
                }
            }
        }

        // softmax (max-free): p = exp(s*scale) with causal mask; row sums
        float rsum[2][2] = { {0.f, 0.f}, {0.f, 0.f} };
        #pragma unroll
        for (int mt = 0; mt < 2; mt++)
            #pragma unroll
            for (int nt = 0; nt < 4; nt++)
                #pragma unroll
                for (int h = 0; h < 2; h++) {
                    int rloc = mw * 32 + mt * 16 + (lane >> 2) + h * 8;
                    int jb = t * 64 + nw * 32 + nt * 8 + (lane & 3) * 2;
                    int lim = q0 + rloc;
                    float p0 = (jb <= lim) ? __expf(s[mt][nt][h * 2] * scale) : 0.0f;
                    float p1 = (jb + 1 <= lim) ? __expf(s[mt][nt][h * 2 + 1] * scale) : 0.0f;
                    s[mt][nt][h * 2] = p0;
                    s[mt][nt][h * 2 + 1] = p1;
                    rsum[mt][h] += p0 + p1;
                }
        #pragma unroll
        for (int mt = 0; mt < 2; mt++)
            #pragma unroll
            for (int h = 0; h < 2; h++) {
                float v = rsum[mt][h];
                v += __shfl_xor_sync(0xffffffffu, v, 1);
                v += __shfl_xor_sync(0xffffffffu, v, 2);
                if ((lane & 3) == 0)
                    atomicAdd(&ls[mw * 32 + mt * 16 + (lane >> 2) + h * 8], v);
            }
        // P -> smem bf16 hi/lo
        #pragma unroll
        for (int mt = 0; mt < 2; mt++)
            #pragma unroll
            for (int nt = 0; nt < 4; nt++)
                #pragma unroll
                for (int h = 0; h < 2; h++) {
                    int r = mw * 32 + mt * 16 + (lane >> 2) + h * 8;
                    int c = nw * 32 + nt * 8 + (lane & 3) * 2;
                    uint32_t hw, lw;
                    split2(s[mt][nt][h * 2], s[mt][nt][h * 2 + 1], hw, lw);
                    uint32_t off = SWZ((uint32_t)(r * 128 + c * 2));
                    *(uint32_t*)(sm + 131072 + off) = hw;
                    *(uint32_t*)(sm + 147456 + off) = lw;
                }
        __syncthreads();

        // O += P V
        #pragma unroll
        for (int pass = 0; pass < 3; pass++) {
            uint32_t ab = sb + (pass == 1 ? 147456u : 131072u);
            uint32_t bb = sb + (pass == 2 ? 114688u : 98304u);
            #pragma unroll
            for (int kk = 0; kk < 4; kk++) {
                int bc = kk * 32;
                uint32_t a[2][4];
                #pragma unroll
                for (int mt = 0; mt < 2; mt++)
                    ldsm4(a[mt], aAddr(ab, mw * 32 + mt * 16, bc, lane));
                #pragma unroll
                for (int p2 = 0; p2 < 4; p2++) {
                    uint32_t bf[4];
                    ldsm4(bf, bAddr(bb, nw * 64 + p2 * 16, bc, lane));
                    #pragma unroll
                    for (int mt = 0; mt < 2; mt++) {
                        mma_bf16(o[mt][p2 * 2], a[mt], bf[0], bf[1]);
                        mma_bf16(o[mt][p2 * 2 + 1], a[mt], bf[2], bf[3]);
                    }
                }
            }
        }
        __syncthreads();
    }

    // epilogue: normalize, write fp32
    float* op = out + ((size_t)(b * Tn + q0)) * Hn;
    #pragma unroll
    for (int mt = 0; mt < 2; mt++)
        #pragma unroll
        for (int h = 0; h < 2; h++) {
            int r = mw * 32 + mt * 16 + (lane >> 2) + h * 8;
            float inv = 1.0f / ls[r];
            #pragma unroll
            for (int nt = 0; nt < 8; nt++) {
                int c = nw * 64 + nt * 8 + (lane & 3) * 2;
                float2 w = { o[mt][nt][h * 2] * inv, o[mt][nt][h * 2 + 1] * inv };
                *(float2*)(op + (size_t)r * Hn + c) = w;
            }
        }
}

extern "C" void kernel_launch(void* const* d_in, const int* in_sizes, int n_in,
                              void* d_out, int out_size)
{
    const float* x  = (const float*)d_in[0];
    const float* Wq = (const float*)d_in[1];
    const float* Wk = (const float*)d_in[2];
    const float* Wv = (const float*)d_in[3];
    float* out = (float*)d_out;

    cudaFuncSetAttribute(proj_mma, cudaFuncAttributeMaxDynamicSharedMemorySize, PJ_SMEM);
    cudaFuncSetAttribute(attn_mma, cudaFuncAttributeMaxDynamicSharedMemorySize, AT_SMEM);

    convW<<<1536, 256>>>(Wq, Wk, Wv);
    proj_mma<<<BT / 128, 384, PJ_SMEM>>>(x);
    attn_mma<<<dim3(Tn / 128, Bn), 256, AT_SMEM>>>(out);
}

// round 7
// speedup vs baseline: 1.7224x; 1.0020x over previous
#include <cuda_runtime.h>
#include <cuda_bf16.h>
#include <cstdint>
#include <math.h>

#define Bn 8
#define Tn 2048
#define Cn 1024
#define Hn 128
#define BT (Bn * Tn)

// bf16 hi/lo scratch (device globals, no allocation)
__device__ __nv_bfloat16 g_Qh[BT * Hn], g_Ql[BT * Hn];
__device__ __nv_bfloat16 g_Kh[BT * Hn], g_Kl[BT * Hn];
__device__ __nv_bfloat16 g_Vh[BT * Hn], g_Vl[BT * Hn];
__device__ __nv_bfloat16 g_Wh[3 * Hn * Cn], g_Wl[3 * Hn * Cn];  // [o][n][k]

// ---------------- helpers ----------------
#define SWZ(x) ((x) ^ (((x) >> 3) & 0x70))

__device__ __forceinline__ uint32_t smem_u32(const void* p) {
    uint32_t a;
    asm("{ .reg .u64 t; cvta.to.shared.u64 t, %1; cvt.u32.u64 %0, t; }" : "=r"(a) : "l"(p));
    return a;
}
// pack two fp32 -> bf16x2 (lo = first arg, hi = second)
__device__ __forceinline__ uint32_t pack2(float lo, float hi) {
    uint32_t r;
    asm("cvt.rn.bf16x2.f32 %0, %1, %2;" : "=r"(r) : "f"(hi), "f"(lo));
    return r;
}
// split (a,b) fp32 pair into bf16 hi word + bf16 lo word
__device__ __forceinline__ void split2(float a, float b, uint32_t& h, uint32_t& l) {
    float ah = __bfloat162float(__float2bfloat16(a));
    float bh = __bfloat162float(__float2bfloat16(b));
    h = pack2(ah, bh);
    l = pack2(a - ah, b - bh);
}
__device__ __forceinline__ void ldsm4(uint32_t* r, uint32_t addr) {
    asm volatile("ldmatrix.sync.aligned.m8n8.x4.shared.b16 {%0,%1,%2,%3}, [%4];"
                 : "=r"(r[0]), "=r"(r[1]), "=r"(r[2]), "=r"(r[3]) : "r"(addr));
}
__device__ __forceinline__ void mma_bf16(float* d, const uint32_t* a, uint32_t b0, uint32_t b1) {
    asm volatile("mma.sync.aligned.m16n8k16.row.col.f32.bf16.bf16.f32 "
                 "{%0,%1,%2,%3}, {%4,%5,%6,%7}, {%8,%9}, {%0,%1,%2,%3};"
                 : "+f"(d[0]), "+f"(d[1]), "+f"(d[2]), "+f"(d[3])
                 : "r"(a[0]), "r"(a[1]), "r"(a[2]), "r"(a[3]), "r"(b0), "r"(b1));
}
// ldmatrix address for A-operand 16x16 tile at (r0, bytecol), 128B-pitch tile
__device__ __forceinline__ uint32_t aAddr(uint32_t base, int r0, int bc, int lane) {
    int r = r0 + (lane & 15);
    int c = bc + ((lane >> 4) << 4);
    return base + SWZ((uint32_t)(r * 128 + c));
}
// ldmatrix address for B-operand x4 (two n8 tiles) at (n0, bytecol)
__device__ __forceinline__ uint32_t bAddr(uint32_t base, int n0, int bc, int lane) {
    int r = n0 + (lane & 7) + ((lane >> 4) << 3);
    int c = bc + (((lane >> 3) & 1) << 4);
    return base + SWZ((uint32_t)(r * 128 + c));
}

// ============================================================================
// convW: W[o][k][n] fp32 -> g_Wh/g_Wl [o][n][k] bf16 hi/lo
// ============================================================================
__global__ void convW(const float* __restrict__ Wq, const float* __restrict__ Wk,
                      const float* __restrict__ Wv) {
    int idx = blockIdx.x * 256 + threadIdx.x;     // 3*1024*128 total
    int o = idx >> 17, rem = idx & 131071;
    int k = rem >> 7, n = rem & 127;
    const float* W = o == 0 ? Wq : o == 1 ? Wk : Wv;
    float f = W[(size_t)k * Hn + n];
    __nv_bfloat16 h = __float2bfloat16(f);
    size_t dst = ((size_t)o * Hn + n) * Cn + k;
    g_Wh[dst] = h;
    g_Wl[dst] = __float2bfloat16(f - __bfloat162float(h));
}

// ============================================================================
// Projection: 384 thr (12 warps = 4 m-blocks x 3 outputs), CTA = 128 rows.
// smem: XHI 0 (16K), XLO 16384, WHI 32768 (48K), WLO 81920.  K-chunks of 64.
// ============================================================================
#define PJ_SMEM (131072 + 128)

__global__ __launch_bounds__(384, 1) void proj_mma(const float* __restrict__ x) {
    extern __shared__ char smraw[];
    char* sm = (char*)(((uintptr_t)smraw + 127) & ~(uintptr_t)127);
    const uint32_t sb = smem_u32(sm);
    const int tid = threadIdx.x, lane = tid & 31, wid = tid >> 5;
    const int mw = wid & 3, ow = wid >> 2;    // m-block, output index
    const int m0 = blockIdx.x * 128;

    float d[2][16][4];
    #pragma unroll
    for (int i = 0; i < 2; i++)
        #pragma unroll
        for (int j = 0; j < 16; j++)
            #pragma unroll
            for (int e = 0; e < 4; e++) d[i][j][e] = 0.0f;

    for (int kc = 0; kc < 16; kc++) {
        if (kc > 0) __syncthreads();   // mma of prev chunk done before restage
        // stage x chunk (threads 0-255): row = tid/2, 32 k each
        if (tid < 256) {
            int row = tid >> 1, kq = (tid & 1) * 32;
            const float* xp = x + (size_t)(m0 + row) * Cn + kc * 64 + kq;
            #pragma unroll
            for (int g = 0; g < 4; g++) {
                float4 v0 = *(const float4*)(xp + g * 8);
                float4 v1 = *(const float4*)(xp + g * 8 + 4);
                uint4 hi, lo;
                split2(v0.x, v0.y, hi.x, lo.x);
                split2(v0.z, v0.w, hi.y, lo.y);
                split2(v1.x, v1.y, hi.z, lo.z);
                split2(v1.z, v1.w, hi.w, lo.w);
                uint32_t off = (uint32_t)(row * 128 + kq * 2 + g * 16);
                *(uint4*)(sm + SWZ(off)) = hi;
                *(uint4*)(sm + 16384 + SWZ(off)) = lo;
            }
        }
        // stage W chunk (all 384 threads, 1 row each: 64 bf16 hi + lo)
        {
            const uint4* wh = (const uint4*)(g_Wh + (size_t)tid * Cn + kc * 64);
            const uint4* wl = (const uint4*)(g_Wl + (size_t)tid * Cn + kc * 64);
            #pragma unroll
            for (int i = 0; i < 8; i++) {
                uint32_t off = (uint32_t)(tid * 128 + i * 16);
                *(uint4*)(sm + 32768 + SWZ(off)) = wh[i];
                *(uint4*)(sm + 81920 + SWZ(off)) = wl[i];
            }
        }
        __syncthreads();

        #pragma unroll
        for (int pass = 0; pass < 3; pass++) {
            const uint32_t ab = sb + (pass == 1 ? 16384u : 0u);
            const uint32_t bb = sb + (pass == 2 ? 81920u : 32768u);
            #pragma unroll
            for (int kk = 0; kk < 4; kk++) {
                uint32_t a[2][4];
                #pragma unroll
                for (int mt = 0; mt < 2; mt++)
                    ldsm4(a[mt], aAddr(ab, mw * 32 + mt * 16, kk * 32, lane));
                #pragma unroll
                for (int p2 = 0; p2 < 8; p2++) {
                    uint32_t bf[4];
                    ldsm4(bf, bAddr(bb, ow * 128 + p2 * 16, kk * 32, lane));
                    #pragma unroll
                    for (int mt = 0; mt < 2; mt++) {
                        mma_bf16(d[mt][p2 * 2], a[mt], bf[0], bf[1]);
                        mma_bf16(d[mt][p2 * 2 + 1], a[mt], bf[2], bf[3]);
                    }
                }
            }
        }
    }

    // epilogue: split to bf16 hi/lo, write packed pairs
    __nv_bfloat16* oh = ow == 0 ? g_Qh : ow == 1 ? g_Kh : g_Vh;
    __nv_bfloat16* ol = ow == 0 ? g_Ql : ow == 1 ? g_Kl : g_Vl;
    #pragma unroll
    for (int mt = 0; mt < 2; mt++)
        #pragma unroll
        for (int h = 0; h < 2; h++) {
            int r = m0 + mw * 32 + mt * 16 + (lane >> 2) + h * 8;
            #pragma unroll
            for (int nt = 0; nt < 16; nt++) {
                int c = nt * 8 + (lane & 3) * 2;
                uint32_t hw, lw;
                split2(d[mt][nt][h * 2], d[mt][nt][h * 2 + 1], hw, lw);
                size_t byt = ((size_t)r * Hn + c) * 2;
                *(uint32_t*)((char*)oh + byt) = hw;
                *(uint32_t*)((char*)ol + byt) = lw;
            }
        }
}

// ============================================================================
// Attention: 256 thr (8 warps: 4 m-blocks x 2 n-blocks), CTA = 128 q-rows.
// 64-key tiles, max-free softmax, O in fp32 fragments across tiles.
// smem: Q hi 0/16384 (halves), Q lo 32768/49152, K hi 65536/73728,
//       K lo 81920/90112, Vt hi 98304, Vt lo 114688, P hi 131072, P lo 147456,
//       l[128] 163840.
// ============================================================================
#define AT_SMEM (163840 + 512 + 128)

__global__ __launch_bounds__(256, 1) void attn_mma(float* __restrict__ out) {
    extern __shared__ char smraw[];
    char* sm = (char*)(((uintptr_t)smraw + 127) & ~(uintptr_t)127);
    const uint32_t sb = smem_u32(sm);
    float* ls = (float*)(sm + 163840);
    const int tid = threadIdx.x, lane = tid & 31, wid = tid >> 5;
    const int mw = wid >> 1, nw = wid & 1;
    const int b = blockIdx.y, qi = blockIdx.x, q0 = qi * 128;

    if (tid < 128) ls[tid] = 0.0f;

    // stage Q (hi/lo, two h-halves)
    {
        int row = tid >> 1, half = tid & 1;
        size_t g = ((size_t)(b * Tn + q0 + row)) * Hn + half * 64;
        const uint4* qh = (const uint4*)(g_Qh + g);
        const uint4* ql = (const uint4*)(g_Ql + g);
        #pragma unroll
        for (int i = 0; i < 8; i++) {
            uint32_t off = SWZ((uint32_t)(row * 128 + i * 16));
            *(uint4*)(sm + half * 16384 + off) = qh[i];
            *(uint4*)(sm + 32768 + half * 16384 + off) = ql[i];
        }
    }

    float o[2][8][4];
    #pragma unroll
    for (int i = 0; i < 2; i++)
        #pragma unroll
        for (int j = 0; j < 8; j++)
            #pragma unroll
            for (int e = 0; e < 4; e++) o[i][j][e] = 0.0f;

    const float scale = 0.08838834764831845f;  // 1/sqrt(128)
    const int ntiles = 2 * qi + 2;

    for (int t = 0; t < ntiles; t++) {
        // stage K tile (row-major halves)
        {
            int row = tid >> 2, quad = tid & 3;
            size_t g = ((size_t)(b * Tn + t * 64 + row)) * Hn + quad * 32;
            const uint4* kh = (const uint4*)(g_Kh + g);
            const uint4* kl = (const uint4*)(g_Kl + g);
            int half = quad >> 1, hin = (quad & 1) * 64;
            #pragma unroll
            for (int i = 0; i < 4; i++) {
                uint32_t off = SWZ((uint32_t)(row * 128 + hin + i * 16));
                *(uint4*)(sm + 65536 + half * 8192 + off) = kh[i];
                *(uint4*)(sm + 81920 + half * 8192 + off) = kl[i];
            }
        }
        // stage V transposed: Vt[h][key]
        {
            int key = tid >> 2, quad = tid & 3;
            size_t g = ((size_t)(b * Tn + t * 64 + key)) * Hn + quad * 32;
            const uint4* vh4 = (const uint4*)(g_Vh + g);
            const uint4* vl4 = (const uint4*)(g_Vl + g);
            uint4 vh[4] = { vh4[0], vh4[1], vh4[2], vh4[3] };
            uint4 vl[4] = { vl4[0], vl4[1], vl4[2], vl4[3] };
            const uint16_t* hs = (const uint16_t*)vh;
            const uint16_t* lsrc = (const uint16_t*)vl;
            #pragma unroll
            for (int i = 0; i < 32; i++) {
                uint32_t off = SWZ((uint32_t)((quad * 32 + i) * 128 + key * 2));
                *(uint16_t*)(sm + 98304 + off) = hs[i];
                *(uint16_t*)(sm + 114688 + off) = lsrc[i];
            }
        }
        __syncthreads();

        // S = Q K^T
        float s[2][4][4];
        #pragma unroll
        for (int i = 0; i < 2; i++)
            #pragma unroll
            for (int j = 0; j < 4; j++)
                #pragma unroll
                for (int e = 0; e < 4; e++) s[i][j][e] = 0.0f;

        #pragma unroll
        for (int pass = 0; pass < 3; pass++) {
            uint32_t ab = sb + (pass == 1 ? 32768u : 0u);
            uint32_t bb = sb + (pass == 2 ? 81920u : 65536u);
            #pragma unroll
            for (int kk = 0; kk < 8; kk++) {
                uint32_t abase = ab + (uint32_t)(kk >> 2) * 16384u;
                uint32_t bbase = bb + (uint32_t)(kk >> 2) * 8192u;
                int bc = (kk & 3) * 32;
                uint32_t a[2][4];
                #pragma unroll
                for (int mt = 0; mt < 2; mt++)
                    ldsm4(a[mt], aAddr(abase, mw * 32 + mt * 16, bc, lane));
                #pragma unroll
                for (int p2 = 0; p2 < 2; p2++) {
                    uint32_t bf[4];
                    ldsm4(bf, bAddr(bbase, nw * 32 + p2 * 16, bc, lane));
                    #pragma unroll
                    for (int mt = 0; mt < 2; mt++) {
                        mma_bf16(s[mt][p2 * 2], a[mt], bf[0], bf[1]);
                        mma_bf16(s[mt][p2 * 2 + 1], a[mt], bf[2], bf[3]);
                    }
                }
            }
        }

        // softmax (max-free): p = exp(s*scale) with causal mask; row sums
        float rsum[2][2] = { {0.f, 0.f}, {0.f, 0.f} };
        #pragma unroll
        for (int mt = 0; mt < 2; mt++)
            #pragma unroll
            for (int nt = 0; nt < 4; nt++)
                #pragma unroll
                for (int h = 0; h < 2; h++) {
                    int rloc = mw * 32 + mt * 16 + (lane >> 2) + h * 8;
                    int jb = t * 64 + nw * 32 + nt * 8 + (lane & 3) * 2;
                    int lim = q0 + rloc;
                    float p0 = (jb <= lim) ? __expf(s[mt][nt][h * 2] * scale) : 0.0f;
                    float p1 = (jb + 1 <= lim) ? __expf(s[mt][nt][h * 2 + 1] * scale) : 0.0f;
                    s[mt][nt][h * 2] = p0;
                    s[mt][nt][h * 2 + 1] = p1;
                    rsum[mt][h] += p0 + p1;
                }
        #pragma unroll
        for (int mt = 0; mt < 2; mt++)
            #pragma unroll
            for (int h = 0; h < 2; h++) {
                float v = rsum[mt][h];
                v += __shfl_xor_sync(0xffffffffu, v, 1);
                v += __shfl_xor_sync(0xffffffffu, v, 2);
                if ((lane & 3) == 0)
                    atomicAdd(&ls[mw * 32 + mt * 16 + (lane >> 2) + h * 8], v);
            }
        // P -> smem bf16 hi/lo
        #pragma unroll
        for (int mt = 0; mt < 2; mt++)
            #pragma unroll
            for (int nt = 0; nt < 4; nt++)
                #pragma unroll
                for (int h = 0; h < 2; h++) {
                    int r = mw * 32 + mt * 16 + (lane >> 2) + h * 8;
                    int c = nw * 32 + nt * 8 + (lane & 3) * 2;
                    uint32_t hw, lw;
                    split2(s[mt][nt][h * 2], s[mt][nt][h * 2 + 1], hw, lw);
                    uint32_t off = SWZ((uint32_t)(r * 128 + c * 2));
                    *(uint32_t*)(sm + 131072 + off) = hw;
                    *(uint32_t*)(sm + 147456 + off) = lw;
                }
        __syncthreads();

        // O += P V
        #pragma unroll
        for (int pass = 0; pass < 3; pass++) {
            uint32_t ab = sb + (pass == 1 ? 147456u : 131072u);
            uint32_t bb = sb + (pass == 2 ? 114688u : 98304u);
            #pragma unroll
            for (int kk = 0; kk < 4; kk++) {
                int bc = kk * 32;
                uint32_t a[2][4];
                #pragma unroll
                for (int mt = 0; mt < 2; mt++)
                    ldsm4(a[mt], aAddr(ab, mw * 32 + mt * 16, bc, lane));
                #pragma unroll
                for (int p2 = 0; p2 < 4; p2++) {
                    uint32_t bf[4];
                    ldsm4(bf, bAddr(bb, nw * 64 + p2 * 16, bc, lane));
                    #pragma unroll
                    for (int mt = 0; mt < 2; mt++) {
                        mma_bf16(o[mt][p2 * 2], a[mt], bf[0], bf[1]);
                        mma_bf16(o[mt][p2 * 2 + 1], a[mt], bf[2], bf[3]);
                    }
                }
            }
        }
        __syncthreads();
    }

    // epilogue: normalize, write fp32
    float* op = out + ((size_t)(b * Tn + q0)) * Hn;
    #pragma unroll
    for (int mt = 0; mt < 2; mt++)
        #pragma unroll
        for (int h = 0; h < 2; h++) {
            int r = mw * 32 + mt * 16 + (lane >> 2) + h * 8;
            float inv = 1.0f / ls[r];
            #pragma unroll
            for (int nt = 0; nt < 8; nt++) {
                int c = nw * 64 + nt * 8 + (lane & 3) * 2;
                float2 w = { o[mt][nt][h * 2] * inv, o[mt][nt][h * 2 + 1] * inv };
                *(float2*)(op + (size_t)r * Hn + c) = w;
            }
        }
}

extern "C" void kernel_launch(void* const* d_in, const int* in_sizes, int n_in,
                              void* d_out, int out_size)
{
    const float* x  = (const float*)d_in[0];
    const float* Wq = (const float*)d_in[1];
    const float* Wk = (const float*)d_in[2];
    const float* Wv = (const float*)d_in[3];
    float* out = (float*)d_out;

    cudaFuncSetAttribute(proj_mma, cudaFuncAttributeMaxDynamicSharedMemorySize, PJ_SMEM);
    cudaFuncSetAttribute(attn_mma, cudaFuncAttributeMaxDynamicSharedMemorySize, AT_SMEM);

    convW<<<1536, 256>>>(Wq, Wk, Wv);
    proj_mma<<<BT / 128, 384, PJ_SMEM>>>(x);
    attn_mma<<<dim3(Tn / 128, Bn), 256, AT_SMEM>>>(out);
}

// round 8
// speedup vs baseline: 2.5127x; 1.4588x over previous
#include <cuda_runtime.h>
#include <cuda_bf16.h>
#include <cstdint>
#include <math.h>

#define Bn 8
#define Tn 2048
#define Cn 1024
#define Hn 128
#define BT (Bn * Tn)

// bf16 hi/lo scratch (device globals, no allocation)
__device__ __nv_bfloat16 g_Qh[BT * Hn], g_Ql[BT * Hn];
__device__ __nv_bfloat16 g_Kh[BT * Hn], g_Kl[BT * Hn];
__device__ __nv_bfloat16 g_Vh[BT * Hn], g_Vl[BT * Hn];
__device__ __nv_bfloat16 g_Wh[3 * Hn * Cn], g_Wl[3 * Hn * Cn];  // [o][n][k]
__device__ __nv_bfloat16 g_Xh[BT * Cn], g_Xl[BT * Cn];          // [m][k]

// ---------------- helpers ----------------
#define SWZ(x) ((x) ^ (((x) >> 3) & 0x70))

__device__ __forceinline__ uint32_t smem_u32(const void* p) {
    uint32_t a;
    asm("{ .reg .u64 t; cvta.to.shared.u64 t, %1; cvt.u32.u64 %0, t; }" : "=r"(a) : "l"(p));
    return a;
}
__device__ __forceinline__ uint32_t pack2(float lo, float hi) {
    uint32_t r;
    asm("cvt.rn.bf16x2.f32 %0, %1, %2;" : "=r"(r) : "f"(hi), "f"(lo));
    return r;
}
__device__ __forceinline__ void split2(float a, float b, uint32_t& h, uint32_t& l) {
    float ah = __bfloat162float(__float2bfloat16(a));
    float bh = __bfloat162float(__float2bfloat16(b));
    h = pack2(ah, bh);
    l = pack2(a - ah, b - bh);
}
__device__ __forceinline__ void ldsm4(uint32_t* r, uint32_t addr) {
    asm volatile("ldmatrix.sync.aligned.m8n8.x4.shared.b16 {%0,%1,%2,%3}, [%4];"
                 : "=r"(r[0]), "=r"(r[1]), "=r"(r[2]), "=r"(r[3]) : "r"(addr));
}
__device__ __forceinline__ void ldsm4t(uint32_t* r, uint32_t addr) {
    asm volatile("ldmatrix.sync.aligned.m8n8.x4.trans.shared.b16 {%0,%1,%2,%3}, [%4];"
                 : "=r"(r[0]), "=r"(r[1]), "=r"(r[2]), "=r"(r[3]) : "r"(addr));
}
__device__ __forceinline__ void mma_bf16(float* d, const uint32_t* a, uint32_t b0, uint32_t b1) {
    asm volatile("mma.sync.aligned.m16n8k16.row.col.f32.bf16.bf16.f32 "
                 "{%0,%1,%2,%3}, {%4,%5,%6,%7}, {%8,%9}, {%0,%1,%2,%3};"
                 : "+f"(d[0]), "+f"(d[1]), "+f"(d[2]), "+f"(d[3])
                 : "r"(a[0]), "r"(a[1]), "r"(a[2]), "r"(a[3]), "r"(b0), "r"(b1));
}
// A-operand 16x16 at (r0, bytecol) in a 128B-pitch tile
__device__ __forceinline__ uint32_t aAddr(uint32_t base, int r0, int bc, int lane) {
    int r = r0 + (lane & 15);
    int c = bc + ((lane >> 4) << 4);
    return base + SWZ((uint32_t)(r * 128 + c));
}
// B-operand x4 (two n8 tiles) from row-major B^T (n rows, k cols), 128B pitch
__device__ __forceinline__ uint32_t bAddr(uint32_t base, int n0, int bc, int lane) {
    int r = n0 + (lane & 7) + ((lane >> 4) << 3);
    int c = bc + (((lane >> 3) & 1) << 4);
    return base + SWZ((uint32_t)(r * 128 + c));
}
// B-operand x4 via trans from row-major V[k][n]: two 8K col-blocks (n>=64)
__device__ __forceinline__ uint32_t vAddr(uint32_t base, int n0, int k0, int lane) {
    int g = lane >> 3, li = lane & 7;
    int kr = k0 + ((g & 1) << 3) + li;
    int nc = n0 + ((g >> 1) << 3);
    return base + ((uint32_t)(nc >> 6) << 13) + SWZ((uint32_t)(kr * 128 + (nc & 63) * 2));
}
__device__ __forceinline__ void cpa16(uint32_t dst, const void* src) {
    asm volatile("cp.async.cg.shared.global [%0], [%1], 16;" :: "r"(dst), "l"(src));
}
#define CPA_COMMIT() asm volatile("cp.async.commit_group;" ::: "memory")
#define CPA_WAIT(n)  asm volatile("cp.async.wait_group %0;" :: "n"(n) : "memory")

// ============================================================================
// convW: W[o][k][n] fp32 -> g_Wh/g_Wl [o][n][k];  convX: x -> g_Xh/g_Xl
// ============================================================================
__global__ void convW(const float* __restrict__ Wq, const float* __restrict__ Wk,
                      const float* __restrict__ Wv) {
    int idx = blockIdx.x * 256 + threadIdx.x;
    int o = idx >> 17, rem = idx & 131071;
    int k = rem >> 7, n = rem & 127;
    const float* W = o == 0 ? Wq : o == 1 ? Wk : Wv;
    float f = W[(size_t)k * Hn + n];
    __nv_bfloat16 h = __float2bfloat16(f);
    size_t dst = ((size_t)o * Hn + n) * Cn + k;
    g_Wh[dst] = h;
    g_Wl[dst] = __float2bfloat16(f - __bfloat162float(h));
}
__global__ void convX(const float* __restrict__ x) {
    size_t idx = (size_t)blockIdx.x * 256 + threadIdx.x;   // over BT*Cn/2
    float2 v = *(const float2*)(x + 2 * idx);
    uint32_t h, l;
    split2(v.x, v.y, h, l);
    *(uint32_t*)((char*)g_Xh + 4 * idx) = h;
    *(uint32_t*)((char*)g_Xl + 4 * idx) = l;
}

// ============================================================================
// Projection: grid (BT/128, 3), 256 thr (8 warps = 4 m x 2 n), k-chunks of 64,
// cp.async double-buffered. Stage: XH 0, XL 16K, WH 32K, WL 48K (64K/stage).
// ============================================================================
#define PJ_SMEM (131072 + 128)

__device__ __forceinline__ void pj_stage(uint32_t sb, int m0, int o, int kc, int tid) {
    uint32_t stg = sb + (uint32_t)(kc & 1) * 65536u;
    const __nv_bfloat16* xs = g_Xh;
    #pragma unroll
    for (int arr = 0; arr < 4; arr++) {
        const __nv_bfloat16* src =
            arr == 0 ? g_Xh : arr == 1 ? g_Xl : arr == 2 ? g_Wh : g_Wl;
        uint32_t dbase = stg + (uint32_t)arr * 16384u;
        #pragma unroll
        for (int i = 0; i < 4; i++) {
            int id = tid * 4 + i;                 // 0..1023
            int row = id >> 3, c = id & 7;        // 128 rows x 8 chunks
            size_t g = (arr < 2)
                ? ((size_t)(m0 + row) * Cn + kc * 64 + c * 8)
                : (((size_t)o * Hn + row) * Cn + kc * 64 + c * 8);
            cpa16(dbase + SWZ((uint32_t)(row * 128 + c * 16)), src + g);
        }
    }
    (void)xs;
}

__global__ __launch_bounds__(256, 1) void proj_mma(void) {
    extern __shared__ char smraw[];
    char* sm = (char*)(((uintptr_t)smraw + 127) & ~(uintptr_t)127);
    const uint32_t sb = smem_u32(sm);
    const int tid = threadIdx.x, lane = tid & 31, wid = tid >> 5;
    const int mw = wid >> 1, nww = wid & 1;
    const int m0 = blockIdx.x * 128, o = blockIdx.y;

    float d[2][8][4];
    #pragma unroll
    for (int i = 0; i < 2; i++)
        #pragma unroll
        for (int j = 0; j < 8; j++)
            #pragma unroll
            for (int e = 0; e < 4; e++) d[i][j][e] = 0.0f;

    pj_stage(sb, m0, o, 0, tid);
    CPA_COMMIT();

    for (int kc = 0; kc < 16; kc++) {
        if (kc + 1 < 16) { pj_stage(sb, m0, o, kc + 1, tid); CPA_COMMIT(); CPA_WAIT(1); }
        else CPA_WAIT(0);
        __syncthreads();

        const uint32_t stg = sb + (uint32_t)(kc & 1) * 65536u;
        #pragma unroll
        for (int pass = 0; pass < 3; pass++) {
            const uint32_t ab = stg + (pass == 1 ? 16384u : 0u);
            const uint32_t bb = stg + (pass == 2 ? 49152u : 32768u);
            #pragma unroll
            for (int kk = 0; kk < 4; kk++) {
                int bc = kk * 32;
                uint32_t a[2][4];
                #pragma unroll
                for (int mt = 0; mt < 2; mt++)
                    ldsm4(a[mt], aAddr(ab, mw * 32 + mt * 16, bc, lane));
                #pragma unroll
                for (int p2 = 0; p2 < 4; p2++) {
                    uint32_t bf[4];
                    ldsm4(bf, bAddr(bb, nww * 64 + p2 * 16, bc, lane));
                    #pragma unroll
                    for (int mt = 0; mt < 2; mt++) {
                        mma_bf16(d[mt][p2 * 2], a[mt], bf[0], bf[1]);
                        mma_bf16(d[mt][p2 * 2 + 1], a[mt], bf[2], bf[3]);
                    }
                }
            }
        }
        __syncthreads();
    }

    __nv_bfloat16* oh = o == 0 ? g_Qh : o == 1 ? g_Kh : g_Vh;
    __nv_bfloat16* ol = o == 0 ? g_Ql : o == 1 ? g_Kl : g_Vl;
    #pragma unroll
    for (int mt = 0; mt < 2; mt++)
        #pragma unroll
        for (int h = 0; h < 2; h++) {
            int r = m0 + mw * 32 + mt * 16 + (lane >> 2) + h * 8;
            #pragma unroll
            for (int nt = 0; nt < 8; nt++) {
                int c = nww * 64 + nt * 8 + (lane & 3) * 2;
                uint32_t hw, lw;
                split2(d[mt][nt][h * 2], d[mt][nt][h * 2 + 1], hw, lw);
                size_t byt = ((size_t)r * Hn + c) * 2;
                *(uint32_t*)((char*)oh + byt) = hw;
                *(uint32_t*)((char*)ol + byt) = lw;
            }
        }
}

// ============================================================================
// Attention: 256 thr (8 warps: 4 m x 2 n), CTA = 128 q-rows, 64-key tiles,
// max-free softmax, cp.async double-buffered K/V, ldmatrix.trans for V.
// smem: QH0 0, QH1 16K, QL0 32K, QL1 48K | stages at 64K,128K:
//       {KH 0, KL 16K, VH 32K, VL 48K} | PH 192K, PL 208K | ls 224K.
// ============================================================================
#define AT_STG0 65536
#define AT_PH   196608
#define AT_PL   212992
#define AT_LS   229376
#define AT_SMEM (229376 + 512 + 128)

__device__ __forceinline__ void at_stage(uint32_t sb, int b, int t, int s, int tid) {
    uint32_t stg = sb + AT_STG0 + (uint32_t)s * 65536u;
    #pragma unroll
    for (int arr = 0; arr < 4; arr++) {
        const __nv_bfloat16* src =
            arr == 0 ? g_Kh : arr == 1 ? g_Kl : arr == 2 ? g_Vh : g_Vl;
        uint32_t dbase = stg + (uint32_t)arr * 16384u;
        #pragma unroll
        for (int i = 0; i < 4; i++) {
            int id = tid * 4 + i;                 // 0..1023
            int row = id >> 4, c = id & 15;       // 64 rows x 16 chunks
            size_t g = (size_t)(b * Tn + t * 64 + row) * Hn + c * 8;
            uint32_t dst = dbase + ((c >= 8) ? 8192u : 0u)
                         + SWZ((uint32_t)(row * 128 + (c & 7) * 16));
            cpa16(dst, src + g);
        }
    }
}

__global__ __launch_bounds__(256, 1) void attn_mma(float* __restrict__ out) {
    extern __shared__ char smraw[];
    char* sm = (char*)(((uintptr_t)smraw + 127) & ~(uintptr_t)127);
    const uint32_t sb = smem_u32(sm);
    float* ls = (float*)(sm + AT_LS);
    const int tid = threadIdx.x, lane = tid & 31, wid = tid >> 5;
    const int mw = wid >> 1, nw = wid & 1;
    const int b = blockIdx.y, qi = blockIdx.x, q0 = qi * 128;

    if (tid < 128) ls[tid] = 0.0f;

    const int ntiles = 2 * qi + 2;
    at_stage(sb, b, 0, 0, tid);
    CPA_COMMIT();

    // stage Q (hi/lo, two h-halves)
    {
        int row = tid >> 1, half = tid & 1;
        size_t g = ((size_t)(b * Tn + q0 + row)) * Hn + half * 64;
        const uint4* qh = (const uint4*)(g_Qh + g);
        const uint4* ql = (const uint4*)(g_Ql + g);
        #pragma unroll
        for (int i = 0; i < 8; i++) {
            uint32_t off = SWZ((uint32_t)(row * 128 + i * 16));
            *(uint4*)(sm + half * 16384 + off) = qh[i];
            *(uint4*)(sm + 32768 + half * 16384 + off) = ql[i];
        }
    }

    float o[2][8][4];
    #pragma unroll
    for (int i = 0; i < 2; i++)
        #pragma unroll
        for (int j = 0; j < 8; j++)
            #pragma unroll
            for (int e = 0; e < 4; e++) o[i][j][e] = 0.0f;

    const float scale = 0.08838834764831845f;  // 1/sqrt(128)

    for (int t = 0; t < ntiles; t++) {
        if (t + 1 < ntiles) { at_stage(sb, b, t + 1, (t + 1) & 1, tid); CPA_COMMIT(); CPA_WAIT(1); }
        else CPA_WAIT(0);
        __syncthreads();

        const uint32_t stg = sb + AT_STG0 + (uint32_t)(t & 1) * 65536u;

        // S = Q K^T
        float s[2][4][4];
        #pragma unroll
        for (int i = 0; i < 2; i++)
            #pragma unroll
            for (int j = 0; j < 4; j++)
                #pragma unroll
                for (int e = 0; e < 4; e++) s[i][j][e] = 0.0f;

        #pragma unroll
        for (int pass = 0; pass < 3; pass++) {
            uint32_t ab = sb + (pass == 1 ? 32768u : 0u);
            uint32_t bb = stg + (pass == 2 ? 16384u : 0u);
            #pragma unroll
            for (int kk = 0; kk < 8; kk++) {
                uint32_t abase = ab + (uint32_t)(kk >> 2) * 16384u;
                uint32_t bbase = bb + (uint32_t)(kk >> 2) * 8192u;
                int bc = (kk & 3) * 32;
                uint32_t a[2][4];
                #pragma unroll
                for (int mt = 0; mt < 2; mt++)
                    ldsm4(a[mt], aAddr(abase, mw * 32 + mt * 16, bc, lane));
                #pragma unroll
                for (int p2 = 0; p2 < 2; p2++) {
                    uint32_t bf[4];
                    ldsm4(bf, bAddr(bbase, nw * 32 + p2 * 16, bc, lane));
                    #pragma unroll
                    for (int mt = 0; mt < 2; mt++) {
                        mma_bf16(s[mt][p2 * 2], a[mt], bf[0], bf[1]);
                        mma_bf16(s[mt][p2 * 2 + 1], a[mt], bf[2], bf[3]);
                    }
                }
            }
        }

        // max-free softmax + row-sum accumulation
        float rsum[2][2] = { {0.f, 0.f}, {0.f, 0.f} };
        #pragma unroll
        for (int mt = 0; mt < 2; mt++)
            #pragma unroll
            for (int nt = 0; nt < 4; nt++)
                #pragma unroll
                for (int h = 0; h < 2; h++) {
                    int rloc = mw * 32 + mt * 16 + (lane >> 2) + h * 8;
                    int jb = t * 64 + nw * 32 + nt * 8 + (lane & 3) * 2;
                    int lim = q0 + rloc;
                    float p0 = (jb <= lim) ? __expf(s[mt][nt][h * 2] * scale) : 0.0f;
                    float p1 = (jb + 1 <= lim) ? __expf(s[mt][nt][h * 2 + 1] * scale) : 0.0f;
                    s[mt][nt][h * 2] = p0;
                    s[mt][nt][h * 2 + 1] = p1;
                    rsum[mt][h] += p0 + p1;
                }
        #pragma unroll
        for (int mt = 0; mt < 2; mt++)
            #pragma unroll
            for (int h = 0; h < 2; h++) {
                float v = rsum[mt][h];
                v += __shfl_xor_sync(0xffffffffu, v, 1);
                v += __shfl_xor_sync(0xffffffffu, v, 2);
                if ((lane & 3) == 0)
                    atomicAdd(&ls[mw * 32 + mt * 16 + (lane >> 2) + h * 8], v);
            }
        // P -> smem bf16 hi/lo
        #pragma unroll
        for (int mt = 0; mt < 2; mt++)
            #pragma unroll
            for (int nt = 0; nt < 4; nt++)
                #pragma unroll
                for (int h = 0; h < 2; h++) {
                    int r = mw * 32 + mt * 16 + (lane >> 2) + h * 8;
                    int c = nw * 32 + nt * 8 + (lane & 3) * 2;
                    uint32_t hw, lw;
                    split2(s[mt][nt][h * 2], s[mt][nt][h * 2 + 1], hw, lw);
                    uint32_t off = SWZ((uint32_t)(r * 128 + c * 2));
                    *(uint32_t*)(sm + AT_PH + off) = hw;
                    *(uint32_t*)(sm + AT_PL + off) = lw;
                }
        __syncthreads();

        // O += P V  (V row-major, B via ldmatrix.trans)
        #pragma unroll
        for (int pass = 0; pass < 3; pass++) {
            uint32_t ab = sb + (pass == 1 ? (uint32_t)AT_PL : (uint32_t)AT_PH);
            uint32_t bb = stg + (pass == 2 ? 49152u : 32768u);
            #pragma unroll
            for (int kk = 0; kk < 4; kk++) {
                int bc = kk * 32;
                uint32_t a[2][4];
                #pragma unroll
                for (int mt = 0; mt < 2; mt++)
                    ldsm4(a[mt], aAddr(ab, mw * 32 + mt * 16, bc, lane));
                #pragma unroll
                for (int p2 = 0; p2 < 4; p2++) {
                    uint32_t bf[4];
                    ldsm4t(bf, vAddr(bb, nw * 64 + p2 * 16, kk * 16, lane));
                    #pragma unroll
                    for (int mt = 0; mt < 2; mt++) {
                        mma_bf16(o[mt][p2 * 2], a[mt], bf[0], bf[1]);
                        mma_bf16(o[mt][p2 * 2 + 1], a[mt], bf[2], bf[3]);
                    }
                }
            }
        }
        __syncthreads();
    }

    // epilogue: normalize, write fp32
    float* op = out + ((size_t)(b * Tn + q0)) * Hn;
    #pragma unroll
    for (int mt = 0; mt < 2; mt++)
        #pragma unroll
        for (int h = 0; h < 2; h++) {
            int r = mw * 32 + mt * 16 + (lane >> 2) + h * 8;
            float inv = 1.0f / ls[r];
            #pragma unroll
            for (int nt = 0; nt < 8; nt++) {
                int c = nw * 64 + nt * 8 + (lane & 3) * 2;
                float2 w = { o[mt][nt][h * 2] * inv, o[mt][nt][h * 2 + 1] * inv };
                *(float2*)(op + (size_t)r * Hn + c) = w;
            }
        }
}

extern "C" void kernel_launch(void* const* d_in, const int* in_sizes, int n_in,
                              void* d_out, int out_size)
{
    const float* x  = (const float*)d_in[0];
    const float* Wq = (const float*)d_in[1];
    const float* Wk = (const float*)d_in[2];
    const float* Wv = (const float*)d_in[3];
    float* out = (float*)d_out;

    cudaFuncSetAttribute(proj_mma, cudaFuncAttributeMaxDynamicSharedMemorySize, PJ_SMEM);
    cudaFuncSetAttribute(attn_mma, cudaFuncAttributeMaxDynamicSharedMemorySize, AT_SMEM);

    convW<<<1536, 256>>>(Wq, Wk, Wv);
    convX<<<BT * Cn / 512, 256>>>(x);
    proj_mma<<<dim3(BT / 128, 3), 256, PJ_SMEM>>>();
    attn_mma<<<dim3(Tn / 128, Bn), 256, AT_SMEM>>>(out);
}

// round 9
// speedup vs baseline: 3.6140x; 1.4383x over previous
#include <cuda_runtime.h>
#include <cuda_bf16.h>
#include <cstdint>
#include <math.h>

#define Bn 8
#define Tn 2048
#define Cn 1024
#define Hn 128
#define BT (Bn * Tn)

// bf16 hi/lo scratch (device globals, no allocation)
__device__ __nv_bfloat16 g_Qh[BT * Hn], g_Ql[BT * Hn];
__device__ __nv_bfloat16 g_Kh[BT * Hn], g_Kl[BT * Hn];
__device__ __nv_bfloat16 g_Vh[BT * Hn], g_Vl[BT * Hn];
__device__ __nv_bfloat16 g_Wh[3 * Hn * Cn], g_Wl[3 * Hn * Cn];  // [o][n][k]
__device__ __nv_bfloat16 g_Xh[BT * Cn], g_Xl[BT * Cn];          // [m][k]

// ---------------- helpers ----------------
#define SWZ(x) ((x) ^ (((x) >> 3) & 0x70))

__device__ __forceinline__ uint32_t smem_u32(const void* p) {
    uint32_t a;
    asm("{ .reg .u64 t; cvta.to.shared.u64 t, %1; cvt.u32.u64 %0, t; }" : "=r"(a) : "l"(p));
    return a;
}
__device__ __forceinline__ uint32_t pack2(float lo, float hi) {
    uint32_t r;
    asm("cvt.rn.bf16x2.f32 %0, %1, %2;" : "=r"(r) : "f"(hi), "f"(lo));
    return r;
}
__device__ __forceinline__ void split2(float a, float b, uint32_t& h, uint32_t& l) {
    float ah = __bfloat162float(__float2bfloat16(a));
    float bh = __bfloat162float(__float2bfloat16(b));
    h = pack2(ah, bh);
    l = pack2(a - ah, b - bh);
}
__device__ __forceinline__ void ldsm4(uint32_t* r, uint32_t addr) {
    asm volatile("ldmatrix.sync.aligned.m8n8.x4.shared.b16 {%0,%1,%2,%3}, [%4];"
                 : "=r"(r[0]), "=r"(r[1]), "=r"(r[2]), "=r"(r[3]) : "r"(addr));
}
__device__ __forceinline__ void ldsm4t(uint32_t* r, uint32_t addr) {
    asm volatile("ldmatrix.sync.aligned.m8n8.x4.trans.shared.b16 {%0,%1,%2,%3}, [%4];"
                 : "=r"(r[0]), "=r"(r[1]), "=r"(r[2]), "=r"(r[3]) : "r"(addr));
}
__device__ __forceinline__ void mma_bf16(float* d, const uint32_t* a, uint32_t b0, uint32_t b1) {
    asm volatile("mma.sync.aligned.m16n8k16.row.col.f32.bf16.bf16.f32 "
                 "{%0,%1,%2,%3}, {%4,%5,%6,%7}, {%8,%9}, {%0,%1,%2,%3};"
                 : "+f"(d[0]), "+f"(d[1]), "+f"(d[2]), "+f"(d[3])
                 : "r"(a[0]), "r"(a[1]), "r"(a[2]), "r"(a[3]), "r"(b0), "r"(b1));
}
// A-operand 16x16 at (r0, bytecol) in a 128B-pitch tile
__device__ __forceinline__ uint32_t aAddr(uint32_t base, int r0, int bc, int lane) {
    int r = r0 + (lane & 15);
    int c = bc + ((lane >> 4) << 4);
    return base + SWZ((uint32_t)(r * 128 + c));
}
// B-operand x4 (two n8 tiles) from row-major B^T (n rows, k cols), 128B pitch
__device__ __forceinline__ uint32_t bAddr(uint32_t base, int n0, int bc, int lane) {
    int r = n0 + (lane & 7) + ((lane >> 4) << 3);
    int c = bc + (((lane >> 3) & 1) << 4);
    return base + SWZ((uint32_t)(r * 128 + c));
}
// B-operand x4 via trans from row-major V[k][n]: two 8K col-blocks (n>=64)
__device__ __forceinline__ uint32_t vAddr(uint32_t base, int n0, int k0, int lane) {
    int g = lane >> 3, li = lane & 7;
    int kr = k0 + ((g & 1) << 3) + li;
    int nc = n0 + ((g >> 1) << 3);
    return base + ((uint32_t)(nc >> 6) << 13) + SWZ((uint32_t)(kr * 128 + (nc & 63) * 2));
}
__device__ __forceinline__ void cpa16(uint32_t dst, const void* src) {
    asm volatile("cp.async.cg.shared.global [%0], [%1], 16;" :: "r"(dst), "l"(src));
}
#define CPA_COMMIT() asm volatile("cp.async.commit_group;" ::: "memory")
#define CPA_WAIT(n)  asm volatile("cp.async.wait_group %0;" :: "n"(n) : "memory")

// ============================================================================
// convW / convX
// ============================================================================
__global__ void convW(const float* __restrict__ Wq, const float* __restrict__ Wk,
                      const float* __restrict__ Wv) {
    int idx = blockIdx.x * 256 + threadIdx.x;
    int o = idx >> 17, rem = idx & 131071;
    int k = rem >> 7, n = rem & 127;
    const float* W = o == 0 ? Wq : o == 1 ? Wk : Wv;
    float f = W[(size_t)k * Hn + n];
    __nv_bfloat16 h = __float2bfloat16(f);
    size_t dst = ((size_t)o * Hn + n) * Cn + k;
    g_Wh[dst] = h;
    g_Wl[dst] = __float2bfloat16(f - __bfloat162float(h));
}
__global__ void convX(const float* __restrict__ x) {
    size_t idx = (size_t)blockIdx.x * 256 + threadIdx.x;   // over BT*Cn/2
    float2 v = *(const float2*)(x + 2 * idx);
    uint32_t h, l;
    split2(v.x, v.y, h, l);
    *(uint32_t*)((char*)g_Xh + 4 * idx) = h;
    *(uint32_t*)((char*)g_Xl + 4 * idx) = l;
}

// ============================================================================
// Projection: grid (BT/128, 3), 512 thr (16 warps = 4m x 4n), k-chunks of 64,
// cp.async double-buffered. Stage: XH 0, XL 16K, WH 32K, WL 48K (64K/stage).
// ============================================================================
#define PJ_SMEM (131072 + 128)

__device__ __forceinline__ void pj_stage(uint32_t sb, int m0, int o, int kc, int tid) {
    uint32_t stg = sb + (uint32_t)(kc & 1) * 65536u;
    #pragma unroll
    for (int arr = 0; arr < 4; arr++) {
        const __nv_bfloat16* src =
            arr == 0 ? g_Xh : arr == 1 ? g_Xl : arr == 2 ? g_Wh : g_Wl;
        uint32_t dbase = stg + (uint32_t)arr * 16384u;
        #pragma unroll
        for (int i = 0; i < 2; i++) {
            int id = tid * 2 + i;                 // 0..1023
            int row = id >> 3, c = id & 7;        // 128 rows x 8 chunks
            size_t g = (arr < 2)
                ? ((size_t)(m0 + row) * Cn + kc * 64 + c * 8)
                : (((size_t)o * Hn + row) * Cn + kc * 64 + c * 8);
            cpa16(dbase + SWZ((uint32_t)(row * 128 + c * 16)), src + g);
        }
    }
}

__global__ __launch_bounds__(512, 1) void proj_mma(void) {
    extern __shared__ char smraw[];
    char* sm = (char*)(((uintptr_t)smraw + 127) & ~(uintptr_t)127);
    const uint32_t sb = smem_u32(sm);
    const int tid = threadIdx.x, lane = tid & 31, wid = tid >> 5;
    const int mw = wid >> 2, nww = wid & 3;
    const int m0 = blockIdx.x * 128, o = blockIdx.y;

    float d[2][4][4];
    #pragma unroll
    for (int i = 0; i < 2; i++)
        #pragma unroll
        for (int j = 0; j < 4; j++)
            #pragma unroll
            for (int e = 0; e < 4; e++) d[i][j][e] = 0.0f;

    pj_stage(sb, m0, o, 0, tid);
    CPA_COMMIT();

    for (int kc = 0; kc < 16; kc++) {
        if (kc + 1 < 16) { pj_stage(sb, m0, o, kc + 1, tid); CPA_COMMIT(); CPA_WAIT(1); }
        else CPA_WAIT(0);
        __syncthreads();

        const uint32_t stg = sb + (uint32_t)(kc & 1) * 65536u;
        #pragma unroll
        for (int pass = 0; pass < 3; pass++) {
            const uint32_t ab = stg + (pass == 1 ? 16384u : 0u);
            const uint32_t bb = stg + (pass == 2 ? 49152u : 32768u);
            #pragma unroll
            for (int kk = 0; kk < 4; kk++) {
                int bc = kk * 32;
                uint32_t a[2][4];
                #pragma unroll
                for (int mt = 0; mt < 2; mt++)
                    ldsm4(a[mt], aAddr(ab, mw * 32 + mt * 16, bc, lane));
                #pragma unroll
                for (int p2 = 0; p2 < 2; p2++) {
                    uint32_t bf[4];
                    ldsm4(bf, bAddr(bb, nww * 32 + p2 * 16, bc, lane));
                    #pragma unroll
                    for (int mt = 0; mt < 2; mt++) {
                        mma_bf16(d[mt][p2 * 2], a[mt], bf[0], bf[1]);
                        mma_bf16(d[mt][p2 * 2 + 1], a[mt], bf[2], bf[3]);
                    }
                }
            }
        }
        __syncthreads();
    }

    __nv_bfloat16* oh = o == 0 ? g_Qh : o == 1 ? g_Kh : g_Vh;
    __nv_bfloat16* ol = o == 0 ? g_Ql : o == 1 ? g_Kl : g_Vl;
    #pragma unroll
    for (int mt = 0; mt < 2; mt++)
        #pragma unroll
        for (int h = 0; h < 2; h++) {
            int r = m0 + mw * 32 + mt * 16 + (lane >> 2) + h * 8;
            #pragma unroll
            for (int nt = 0; nt < 4; nt++) {
                int c = nww * 32 + nt * 8 + (lane & 3) * 2;
                uint32_t hw, lw;
                split2(d[mt][nt][h * 2], d[mt][nt][h * 2 + 1], hw, lw);
                size_t byt = ((size_t)r * Hn + c) * 2;
                *(uint32_t*)((char*)oh + byt) = hw;
                *(uint32_t*)((char*)ol + byt) = lw;
            }
        }
}

// ============================================================================
// Attention: 512 thr (16 warps: 4m x 4n), 64-row q-tiles, diagonal pairing:
// CTA bx handles q-tiles (bx, 31-bx) -> uniform 33 key-tiles per CTA.
// Max-free softmax; cp.async double-buffered K/V across the segment boundary.
// smem: QH0 0, QH1 8K, QL0 16K, QL1 24K | stages 32K,96K: {KH 0(2x8K),
//       KL 16K, VH 32K, VL 48K} | PH 160K, PL 168K | ls 176K.
// ============================================================================
#define AT_STG0 32768
#define AT_PH   163840
#define AT_PL   172032
#define AT_LS   180224
#define AT_SMEM (180224 + 256 + 128)

__device__ __forceinline__ void at_stage(uint32_t sb, int b, int t, int s, int tid) {
    uint32_t stg = sb + AT_STG0 + (uint32_t)s * 65536u;
    #pragma unroll
    for (int arr = 0; arr < 4; arr++) {
        const __nv_bfloat16* src =
            arr == 0 ? g_Kh : arr == 1 ? g_Kl : arr == 2 ? g_Vh : g_Vl;
        uint32_t dbase = stg + (uint32_t)arr * 16384u;
        #pragma unroll
        for (int i = 0; i < 2; i++) {
            int id = tid * 2 + i;                 // 0..1023
            int row = id >> 4, c = id & 15;       // 64 rows x 16 chunks
            size_t g = (size_t)(b * Tn + t * 64 + row) * Hn + c * 8;
            uint32_t dst = dbase + ((c >= 8) ? 8192u : 0u)
                         + SWZ((uint32_t)(row * 128 + (c & 7) * 16));
            cpa16(dst, src + g);
        }
    }
}

__global__ __launch_bounds__(512, 1) void attn_mma(float* __restrict__ out) {
    extern __shared__ char smraw[];
    char* sm = (char*)(((uintptr_t)smraw + 127) & ~(uintptr_t)127);
    const uint32_t sb = smem_u32(sm);
    float* ls = (float*)(sm + AT_LS);
    const int tid = threadIdx.x, lane = tid & 31, wid = tid >> 5;
    const int mw = wid >> 2, nw = wid & 3;
    const int b = blockIdx.y;
    const int qt[2] = { (int)blockIdx.x, 31 - (int)blockIdx.x };

    const float scale = 0.08838834764831845f;  // 1/sqrt(128)

    at_stage(sb, b, 0, 0, tid);   // prefetch (seg0, tile0)
    CPA_COMMIT();

    int gi = 0;                   // global tile counter -> buffer parity
    #pragma unroll 1
    for (int seg = 0; seg < 2; seg++) {
        const int q0 = qt[seg] * 64;
        const int nseg = qt[seg] + 1;
        __syncthreads();          // ls/Q reuse safe after previous epilogue

        // stage Q hi/lo (plain stores)
        #pragma unroll
        for (int i = 0; i < 4; i++) {
            int id = tid * 4 + i;                 // 0..2047
            int arr = id >> 10, rem = id & 1023;
            int row = rem >> 4, c = rem & 15;
            int half = c >> 3;
            const __nv_bfloat16* src = (arr ? g_Ql : g_Qh);
            uint4 v = *(const uint4*)(src + (size_t)(b * Tn + q0 + row) * Hn + half * 64 + (c & 7) * 8);
            *(uint4*)(sm + arr * 16384 + half * 8192 + SWZ((uint32_t)(row * 128 + (c & 7) * 16))) = v;
        }
        if (tid < 64) ls[tid] = 0.0f;

        float o[4][4];
        #pragma unroll
        for (int j = 0; j < 4; j++)
            #pragma unroll
            for (int e = 0; e < 4; e++) o[j][e] = 0.0f;

        #pragma unroll 1
        for (int t = 0; t < nseg; t++) {
            const bool more = (t + 1 < nseg) || (seg == 0);
            if (more) {
                at_stage(sb, b, (t + 1 < nseg) ? t + 1 : 0, (gi + 1) & 1, tid);
                CPA_COMMIT(); CPA_WAIT(1);
            } else CPA_WAIT(0);
            __syncthreads();

            const uint32_t stg = sb + AT_STG0 + (uint32_t)(gi & 1) * 65536u;

            // S = Q K^T  (16 rows x 16 cols per warp)
            float s[2][4];
            #pragma unroll
            for (int g = 0; g < 2; g++)
                #pragma unroll
                for (int e = 0; e < 4; e++) s[g][e] = 0.0f;

            #pragma unroll
            for (int pass = 0; pass < 3; pass++) {
                uint32_t ab = sb + (pass == 1 ? 16384u : 0u);
                uint32_t bb = stg + (pass == 2 ? 16384u : 0u);
                #pragma unroll
                for (int kk = 0; kk < 8; kk++) {
                    uint32_t abase = ab + (uint32_t)(kk >> 2) * 8192u;
                    uint32_t bbase = bb + (uint32_t)(kk >> 2) * 8192u;
                    int bc = (kk & 3) * 32;
                    uint32_t a[4], bf[4];
                    ldsm4(a, aAddr(abase, mw * 16, bc, lane));
                    ldsm4(bf, bAddr(bbase, nw * 16, bc, lane));
                    mma_bf16(s[0], a, bf[0], bf[1]);
                    mma_bf16(s[1], a, bf[2], bf[3]);
                }
            }

            // max-free softmax + row-sum accumulation
            const int rbase = mw * 16 + (lane >> 2);
            float rs[2] = { 0.f, 0.f };
            #pragma unroll
            for (int g = 0; g < 2; g++)
                #pragma unroll
                for (int h = 0; h < 2; h++) {
                    int r = rbase + h * 8;
                    int jb = t * 64 + nw * 16 + g * 8 + (lane & 3) * 2;
                    int lim = q0 + r;
                    float p0 = (jb <= lim) ? __expf(s[g][h * 2] * scale) : 0.0f;
                    float p1 = (jb + 1 <= lim) ? __expf(s[g][h * 2 + 1] * scale) : 0.0f;
                    s[g][h * 2] = p0;
                    s[g][h * 2 + 1] = p1;
                    rs[h] += p0 + p1;
                }
            #pragma unroll
            for (int h = 0; h < 2; h++) {
                float v = rs[h];
                v += __shfl_xor_sync(0xffffffffu, v, 1);
                v += __shfl_xor_sync(0xffffffffu, v, 2);
                if ((lane & 3) == 0) atomicAdd(&ls[rbase + h * 8], v);
            }
            // P -> smem bf16 hi/lo
            #pragma unroll
            for (int g = 0; g < 2; g++)
                #pragma unroll
                for (int h = 0; h < 2; h++) {
                    int r = rbase + h * 8;
                    int c = nw * 16 + g * 8 + (lane & 3) * 2;
                    uint32_t hw, lw;
                    split2(s[g][h * 2], s[g][h * 2 + 1], hw, lw);
                    uint32_t off = SWZ((uint32_t)(r * 128 + c * 2));
                    *(uint32_t*)(sm + AT_PH + off) = hw;
                    *(uint32_t*)(sm + AT_PL + off) = lw;
                }
            __syncthreads();

            // O += P V  (V row-major, B via ldmatrix.trans; 16r x 32h per warp)
            #pragma unroll
            for (int pass = 0; pass < 3; pass++) {
                uint32_t ab = sb + (pass == 1 ? (uint32_t)AT_PL : (uint32_t)AT_PH);
                uint32_t bb = stg + (pass == 2 ? 49152u : 32768u);
                #pragma unroll
                for (int kk = 0; kk < 4; kk++) {
                    uint32_t a[4];
                    ldsm4(a, aAddr(ab, mw * 16, kk * 32, lane));
                    #pragma unroll
                    for (int p2 = 0; p2 < 2; p2++) {
                        uint32_t bf[4];
                        ldsm4t(bf, vAddr(bb, nw * 32 + p2 * 16, kk * 16, lane));
                        mma_bf16(o[p2 * 2], a, bf[0], bf[1]);
                        mma_bf16(o[p2 * 2 + 1], a, bf[2], bf[3]);
                    }
                }
            }
            __syncthreads();
            gi++;
        }

        // epilogue: normalize, write fp32
        float* op = out + ((size_t)(b * Tn + q0)) * Hn;
        #pragma unroll
        for (int h = 0; h < 2; h++) {
            int r = mw * 16 + (lane >> 2) + h * 8;
            float inv = 1.0f / ls[r];
            #pragma unroll
            for (int nt = 0; nt < 4; nt++) {
                int c = nw * 32 + nt * 8 + (lane & 3) * 2;
                float2 w = { o[nt][h * 2] * inv, o[nt][h * 2 + 1] * inv };
                *(float2*)(op + (size_t)r * Hn + c) = w;
            }
        }
    }
}

extern "C" void kernel_launch(void* const* d_in, const int* in_sizes, int n_in,
                              void* d_out, int out_size)
{
    const float* x  = (const float*)d_in[0];
    const float* Wq = (const float*)d_in[1];
    const float* Wk = (const float*)d_in[2];
    const float* Wv = (const float*)d_in[3];
    float* out = (float*)d_out;

    cudaFuncSetAttribute(proj_mma, cudaFuncAttributeMaxDynamicSharedMemorySize, PJ_SMEM);
    cudaFuncSetAttribute(attn_mma, cudaFuncAttributeMaxDynamicSharedMemorySize, AT_SMEM);

    convW<<<1536, 256>>>(Wq, Wk, Wv);
    convX<<<BT * Cn / 512, 256>>>(x);
    proj_mma<<<dim3(BT / 128, 3), 512, PJ_SMEM>>>();
    attn_mma<<<dim3(Tn / 128, Bn), 512, AT_SMEM>>>(out);
}

// round 10
// speedup vs baseline: 3.8320x; 1.0603x over previous
#include <cuda_runtime.h>
#include <cuda_bf16.h>
#include <cstdint>
#include <math.h>

#define Bn 8
#define Tn 2048
#define Cn 1024
#define Hn 128
#define BT (Bn * Tn)

// bf16 hi/lo scratch (device globals, no allocation)
__device__ __nv_bfloat16 g_Qh[BT * Hn], g_Ql[BT * Hn];
__device__ __nv_bfloat16 g_Kh[BT * Hn], g_Kl[BT * Hn];
__device__ __nv_bfloat16 g_Vh[BT * Hn], g_Vl[BT * Hn];
__device__ __nv_bfloat16 g_Wh[3 * Hn * Cn], g_Wl[3 * Hn * Cn];  // [o][n][k]
__device__ __nv_bfloat16 g_Xh[BT * Cn], g_Xl[BT * Cn];          // [m][k]

// ---------------- helpers ----------------
#define SWZ(x) ((x) ^ (((x) >> 3) & 0x70))

__device__ __forceinline__ uint32_t smem_u32(const void* p) {
    uint32_t a;
    asm("{ .reg .u64 t; cvta.to.shared.u64 t, %1; cvt.u32.u64 %0, t; }" : "=r"(a) : "l"(p));
    return a;
}
__device__ __forceinline__ uint32_t pack2(float lo, float hi) {
    uint32_t r;
    asm("cvt.rn.bf16x2.f32 %0, %1, %2;" : "=r"(r) : "f"(hi), "f"(lo));
    return r;
}
__device__ __forceinline__ void split2(float a, float b, uint32_t& h, uint32_t& l) {
    float ah = __bfloat162float(__float2bfloat16(a));
    float bh = __bfloat162float(__float2bfloat16(b));
    h = pack2(ah, bh);
    l = pack2(a - ah, b - bh);
}
__device__ __forceinline__ void ldsm4(uint32_t* r, uint32_t addr) {
    asm volatile("ldmatrix.sync.aligned.m8n8.x4.shared.b16 {%0,%1,%2,%3}, [%4];"
                 : "=r"(r[0]), "=r"(r[1]), "=r"(r[2]), "=r"(r[3]) : "r"(addr));
}
__device__ __forceinline__ void ldsm4t(uint32_t* r, uint32_t addr) {
    asm volatile("ldmatrix.sync.aligned.m8n8.x4.trans.shared.b16 {%0,%1,%2,%3}, [%4];"
                 : "=r"(r[0]), "=r"(r[1]), "=r"(r[2]), "=r"(r[3]) : "r"(addr));
}
__device__ __forceinline__ void mma_bf16(float* d, const uint32_t* a, uint32_t b0, uint32_t b1) {
    asm volatile("mma.sync.aligned.m16n8k16.row.col.f32.bf16.bf16.f32 "
                 "{%0,%1,%2,%3}, {%4,%5,%6,%7}, {%8,%9}, {%0,%1,%2,%3};"
                 : "+f"(d[0]), "+f"(d[1]), "+f"(d[2]), "+f"(d[3])
                 : "r"(a[0]), "r"(a[1]), "r"(a[2]), "r"(a[3]), "r"(b0), "r"(b1));
}
// A-operand 16x16 at (r0, bytecol) in a 128B-pitch tile
__device__ __forceinline__ uint32_t aAddr(uint32_t base, int r0, int bc, int lane) {
    int r = r0 + (lane & 15);
    int c = bc + ((lane >> 4) << 4);
    return base + SWZ((uint32_t)(r * 128 + c));
}
// B-operand x4 (two n8 tiles) from row-major B^T (n rows, k cols), 128B pitch
__device__ __forceinline__ uint32_t bAddr(uint32_t base, int n0, int bc, int lane) {
    int r = n0 + (lane & 7) + ((lane >> 4) << 3);
    int c = bc + (((lane >> 3) & 1) << 4);
    return base + SWZ((uint32_t)(r * 128 + c));
}
// B-operand x4 via trans from row-major V[k][n]: two 8K col-blocks (n>=64)
__device__ __forceinline__ uint32_t vAddr(uint32_t base, int n0, int k0, int lane) {
    int g = lane >> 3, li = lane & 7;
    int kr = k0 + ((g & 1) << 3) + li;
    int nc = n0 + ((g >> 1) << 3);
    return base + ((uint32_t)(nc >> 6) << 13) + SWZ((uint32_t)(kr * 128 + (nc & 63) * 2));
}
__device__ __forceinline__ void cpa16(uint32_t dst, const void* src) {
    asm volatile("cp.async.cg.shared.global [%0], [%1], 16;" :: "r"(dst), "l"(src));
}
#define CPA_COMMIT() asm volatile("cp.async.commit_group;" ::: "memory")
#define CPA_WAIT(n)  asm volatile("cp.async.wait_group %0;" :: "n"(n) : "memory")

// ============================================================================
// convW / convX
// ============================================================================
__global__ void convW(const float* __restrict__ Wq, const float* __restrict__ Wk,
                      const float* __restrict__ Wv) {
    int idx = blockIdx.x * 256 + threadIdx.x;
    int o = idx >> 17, rem = idx & 131071;
    int k = rem >> 7, n = rem & 127;
    const float* W = o == 0 ? Wq : o == 1 ? Wk : Wv;
    float f = W[(size_t)k * Hn + n];
    __nv_bfloat16 h = __float2bfloat16(f);
    size_t dst = ((size_t)o * Hn + n) * Cn + k;
    g_Wh[dst] = h;
    g_Wl[dst] = __float2bfloat16(f - __bfloat162float(h));
}
__global__ void convX(const float* __restrict__ x) {
    size_t idx = (size_t)blockIdx.x * 256 + threadIdx.x;   // over BT*Cn/2
    float2 v = *(const float2*)(x + 2 * idx);
    uint32_t h, l;
    split2(v.x, v.y, h, l);
    *(uint32_t*)((char*)g_Xh + 4 * idx) = h;
    *(uint32_t*)((char*)g_Xl + 4 * idx) = l;
}

// ============================================================================
// Projection: grid (BT/128, 3), 512 thr (16 warps = 4m x 4n), k-chunks of 64,
// cp.async double-buffered, fused 3-product inner loop.
// Stage: XH 0, XL 16K, WH 32K, WL 48K (64K/stage).
// ============================================================================
#define PJ_SMEM (131072 + 128)

__device__ __forceinline__ void pj_stage(uint32_t sb, int m0, int o, int kc, int tid) {
    uint32_t stg = sb + (uint32_t)(kc & 1) * 65536u;
    #pragma unroll
    for (int arr = 0; arr < 4; arr++) {
        const __nv_bfloat16* src =
            arr == 0 ? g_Xh : arr == 1 ? g_Xl : arr == 2 ? g_Wh : g_Wl;
        uint32_t dbase = stg + (uint32_t)arr * 16384u;
        #pragma unroll
        for (int i = 0; i < 2; i++) {
            int id = tid * 2 + i;                 // 0..1023
            int row = id >> 3, c = id & 7;        // 128 rows x 8 chunks
            size_t g = (arr < 2)
                ? ((size_t)(m0 + row) * Cn + kc * 64 + c * 8)
                : (((size_t)o * Hn + row) * Cn + kc * 64 + c * 8);
            cpa16(dbase + SWZ((uint32_t)(row * 128 + c * 16)), src + g);
        }
    }
}

__global__ __launch_bounds__(512, 1) void proj_mma(void) {
    extern __shared__ char smraw[];
    char* sm = (char*)(((uintptr_t)smraw + 127) & ~(uintptr_t)127);
    const uint32_t sb = smem_u32(sm);
    const int tid = threadIdx.x, lane = tid & 31, wid = tid >> 5;
    const int mw = wid >> 2, nww = wid & 3;
    const int m0 = blockIdx.x * 128, o = blockIdx.y;

    float d[2][4][4];
    #pragma unroll
    for (int i = 0; i < 2; i++)
        #pragma unroll
        for (int j = 0; j < 4; j++)
            #pragma unroll
            for (int e = 0; e < 4; e++) d[i][j][e] = 0.0f;

    pj_stage(sb, m0, o, 0, tid);
    CPA_COMMIT();

    for (int kc = 0; kc < 16; kc++) {
        if (kc + 1 < 16) { pj_stage(sb, m0, o, kc + 1, tid); CPA_COMMIT(); CPA_WAIT(1); }
        else CPA_WAIT(0);
        __syncthreads();

        const uint32_t stg = sb + (uint32_t)(kc & 1) * 65536u;
        #pragma unroll
        for (int kk = 0; kk < 4; kk++) {
            int bc = kk * 32;
            uint32_t aH[2][4], aL[2][4];
            #pragma unroll
            for (int mt = 0; mt < 2; mt++) {
                ldsm4(aH[mt], aAddr(stg, mw * 32 + mt * 16, bc, lane));
                ldsm4(aL[mt], aAddr(stg + 16384u, mw * 32 + mt * 16, bc, lane));
            }
            #pragma unroll
            for (int p2 = 0; p2 < 2; p2++) {
                uint32_t bH[4], bL[4];
                ldsm4(bH, bAddr(stg + 32768u, nww * 32 + p2 * 16, bc, lane));
                ldsm4(bL, bAddr(stg + 49152u, nww * 32 + p2 * 16, bc, lane));
                #pragma unroll
                for (int mt = 0; mt < 2; mt++) {
                    mma_bf16(d[mt][p2 * 2],     aH[mt], bH[0], bH[1]);
                    mma_bf16(d[mt][p2 * 2 + 1], aH[mt], bH[2], bH[3]);
                    mma_bf16(d[mt][p2 * 2],     aL[mt], bH[0], bH[1]);
                    mma_bf16(d[mt][p2 * 2 + 1], aL[mt], bH[2], bH[3]);
                    mma_bf16(d[mt][p2 * 2],     aH[mt], bL[0], bL[1]);
                    mma_bf16(d[mt][p2 * 2 + 1], aH[mt], bL[2], bL[3]);
                }
            }
        }
        __syncthreads();
    }

    __nv_bfloat16* oh = o == 0 ? g_Qh : o == 1 ? g_Kh : g_Vh;
    __nv_bfloat16* ol = o == 0 ? g_Ql : o == 1 ? g_Kl : g_Vl;
    #pragma unroll
    for (int mt = 0; mt < 2; mt++)
        #pragma unroll
        for (int h = 0; h < 2; h++) {
            int r = m0 + mw * 32 + mt * 16 + (lane >> 2) + h * 8;
            #pragma unroll
            for (int nt = 0; nt < 4; nt++) {
                int c = nww * 32 + nt * 8 + (lane & 3) * 2;
                uint32_t hw, lw;
                split2(d[mt][nt][h * 2], d[mt][nt][h * 2 + 1], hw, lw);
                size_t byt = ((size_t)r * Hn + c) * 2;
                *(uint32_t*)((char*)oh + byt) = hw;
                *(uint32_t*)((char*)ol + byt) = lw;
            }
        }
}

// ============================================================================
// Attention: 512 thr (16 warps: 4m x 4n), 64-row q-tiles, diagonal pairing
// (CTA bx -> q-tiles bx and 31-bx, uniform 33 key-tiles), max-free softmax,
// cp.async double-buffered K/V, fused 3-product inner loops.
// smem: QH0 0, QH1 8K, QL0 16K, QL1 24K | stages 32K,96K: {KH 0(2x8K),
//       KL 16K, VH 32K, VL 48K} | PH 160K, PL 168K | ls 176K.
// ============================================================================
#define AT_STG0 32768
#define AT_PH   163840
#define AT_PL   172032
#define AT_LS   180224
#define AT_SMEM (180224 + 256 + 128)

__device__ __forceinline__ void at_stage(uint32_t sb, int b, int t, int s, int tid) {
    uint32_t stg = sb + AT_STG0 + (uint32_t)s * 65536u;
    #pragma unroll
    for (int arr = 0; arr < 4; arr++) {
        const __nv_bfloat16* src =
            arr == 0 ? g_Kh : arr == 1 ? g_Kl : arr == 2 ? g_Vh : g_Vl;
        uint32_t dbase = stg + (uint32_t)arr * 16384u;
        #pragma unroll
        for (int i = 0; i < 2; i++) {
            int id = tid * 2 + i;                 // 0..1023
            int row = id >> 4, c = id & 15;       // 64 rows x 16 chunks
            size_t g = (size_t)(b * Tn + t * 64 + row) * Hn + c * 8;
            uint32_t dst = dbase + ((c >= 8) ? 8192u : 0u)
                         + SWZ((uint32_t)(row * 128 + (c & 7) * 16));
            cpa16(dst, src + g);
        }
    }
}

__global__ __launch_bounds__(512, 1) void attn_mma(float* __restrict__ out) {
    extern __shared__ char smraw[];
    char* sm = (char*)(((uintptr_t)smraw + 127) & ~(uintptr_t)127);
    const uint32_t sb = smem_u32(sm);
    float* ls = (float*)(sm + AT_LS);
    const int tid = threadIdx.x, lane = tid & 31, wid = tid >> 5;
    const int mw = wid >> 2, nw = wid & 3;
    const int b = blockIdx.y;
    const int qt[2] = { (int)blockIdx.x, 31 - (int)blockIdx.x };

    const float scale = 0.08838834764831845f;  // 1/sqrt(128)

    at_stage(sb, b, 0, 0, tid);   // prefetch (seg0, tile0)
    CPA_COMMIT();

    int gi = 0;                   // global tile counter -> buffer parity
    #pragma unroll 1
    for (int seg = 0; seg < 2; seg++) {
        const int q0 = qt[seg] * 64;
        const int nseg = qt[seg] + 1;
        __syncthreads();          // ls/Q reuse safe after previous epilogue

        // stage Q hi/lo (plain stores)
        #pragma unroll
        for (int i = 0; i < 4; i++) {
            int id = tid * 4 + i;                 // 0..2047
            int arr = id >> 10, rem = id & 1023;
            int row = rem >> 4, c = rem & 15;
            int half = c >> 3;
            const __nv_bfloat16* src = (arr ? g_Ql : g_Qh);
            uint4 v = *(const uint4*)(src + (size_t)(b * Tn + q0 + row) * Hn + half * 64 + (c & 7) * 8);
            *(uint4*)(sm + arr * 16384 + half * 8192 + SWZ((uint32_t)(row * 128 + (c & 7) * 16))) = v;
        }
        if (tid < 64) ls[tid] = 0.0f;

        float o[4][4];
        #pragma unroll
        for (int j = 0; j < 4; j++)
            #pragma unroll
            for (int e = 0; e < 4; e++) o[j][e] = 0.0f;

        #pragma unroll 1
        for (int t = 0; t < nseg; t++) {
            const bool more = (t + 1 < nseg) || (seg == 0);
            if (more) {
                at_stage(sb, b, (t + 1 < nseg) ? t + 1 : 0, (gi + 1) & 1, tid);
                CPA_COMMIT(); CPA_WAIT(1);
            } else CPA_WAIT(0);
            __syncthreads();

            const uint32_t stg = sb + AT_STG0 + (uint32_t)(gi & 1) * 65536u;

            // S = Q K^T, fused 3-product, 3 independent accumulator sets
            float shh[2][4], slh[2][4], shl[2][4];
            #pragma unroll
            for (int g = 0; g < 2; g++)
                #pragma unroll
                for (int e = 0; e < 4; e++) { shh[g][e] = 0.f; slh[g][e] = 0.f; shl[g][e] = 0.f; }

            #pragma unroll
            for (int kk = 0; kk < 8; kk++) {
                uint32_t hb = (uint32_t)(kk >> 2) * 8192u;
                int bc = (kk & 3) * 32;
                uint32_t aH[4], aL[4], bH[4], bL[4];
                ldsm4(aH, aAddr(sb + hb,           mw * 16, bc, lane));
                ldsm4(aL, aAddr(sb + 16384u + hb,  mw * 16, bc, lane));
                ldsm4(bH, bAddr(stg + hb,          nw * 16, bc, lane));
                ldsm4(bL, bAddr(stg + 16384u + hb, nw * 16, bc, lane));
                mma_bf16(shh[0], aH, bH[0], bH[1]);
                mma_bf16(shh[1], aH, bH[2], bH[3]);
                mma_bf16(slh[0], aL, bH[0], bH[1]);
                mma_bf16(slh[1], aL, bH[2], bH[3]);
                mma_bf16(shl[0], aH, bL[0], bL[1]);
                mma_bf16(shl[1], aH, bL[2], bL[3]);
            }

            // max-free softmax + row-sum accumulation
            const int rbase = mw * 16 + (lane >> 2);
            float rs[2] = { 0.f, 0.f };
            float pr[2][4];
            #pragma unroll
            for (int g = 0; g < 2; g++)
                #pragma unroll
                for (int h = 0; h < 2; h++) {
                    int r = rbase + h * 8;
                    int jb = t * 64 + nw * 16 + g * 8 + (lane & 3) * 2;
                    int lim = q0 + r;
                    float z0 = shh[g][h * 2] + slh[g][h * 2] + shl[g][h * 2];
                    float z1 = shh[g][h * 2 + 1] + slh[g][h * 2 + 1] + shl[g][h * 2 + 1];
                    float p0 = (jb <= lim) ? __expf(z0 * scale) : 0.0f;
                    float p1 = (jb + 1 <= lim) ? __expf(z1 * scale) : 0.0f;
                    pr[g][h * 2] = p0;
                    pr[g][h * 2 + 1] = p1;
                    rs[h] += p0 + p1;
                }
            #pragma unroll
            for (int h = 0; h < 2; h++) {
                float v = rs[h];
                v += __shfl_xor_sync(0xffffffffu, v, 1);
                v += __shfl_xor_sync(0xffffffffu, v, 2);
                if ((lane & 3) == 0) atomicAdd(&ls[rbase + h * 8], v);
            }
            // P -> smem bf16 hi/lo
            #pragma unroll
            for (int g = 0; g < 2; g++)
                #pragma unroll
                for (int h = 0; h < 2; h++) {
                    int r = rbase + h * 8;
                    int c = nw * 16 + g * 8 + (lane & 3) * 2;
                    uint32_t hw, lw;
                    split2(pr[g][h * 2], pr[g][h * 2 + 1], hw, lw);
                    uint32_t off = SWZ((uint32_t)(r * 128 + c * 2));
                    *(uint32_t*)(sm + AT_PH + off) = hw;
                    *(uint32_t*)(sm + AT_PL + off) = lw;
                }
            __syncthreads();

            // O += P V, fused 3-product (V row-major, B via ldmatrix.trans)
            #pragma unroll
            for (int kk = 0; kk < 4; kk++) {
                int bc = kk * 32;
                uint32_t aH[4], aL[4];
                ldsm4(aH, aAddr(sb + AT_PH, mw * 16, bc, lane));
                ldsm4(aL, aAddr(sb + AT_PL, mw * 16, bc, lane));
                #pragma unroll
                for (int p2 = 0; p2 < 2; p2++) {
                    uint32_t bH[4], bL[4];
                    ldsm4t(bH, vAddr(stg + 32768u, nw * 32 + p2 * 16, kk * 16, lane));
                    ldsm4t(bL, vAddr(stg + 49152u, nw * 32 + p2 * 16, kk * 16, lane));
                    mma_bf16(o[p2 * 2],     aH, bH[0], bH[1]);
                    mma_bf16(o[p2 * 2 + 1], aH, bH[2], bH[3]);
                    mma_bf16(o[p2 * 2],     aL, bH[0], bH[1]);
                    mma_bf16(o[p2 * 2 + 1], aL, bH[2], bH[3]);
                    mma_bf16(o[p2 * 2],     aH, bL[0], bL[1]);
                    mma_bf16(o[p2 * 2 + 1], aH, bL[2], bL[3]);
                }
            }
            __syncthreads();
            gi++;
        }

        // epilogue: normalize, write fp32
        float* op = out + ((size_t)(b * Tn + q0)) * Hn;
        #pragma unroll
        for (int h = 0; h < 2; h++) {
            int r = mw * 16 + (lane >> 2) + h * 8;
            float inv = 1.0f / ls[r];
            #pragma unroll
            for (int nt = 0; nt < 4; nt++) {
                int c = nw * 32 + nt * 8 + (lane & 3) * 2;
                float2 w = { o[nt][h * 2] * inv, o[nt][h * 2 + 1] * inv };
                *(float2*)(op + (size_t)r * Hn + c) = w;
            }
        }
    }
}

extern "C" void kernel_launch(void* const* d_in, const int* in_sizes, int n_in,
                              void* d_out, int out_size)
{
    const float* x  = (const float*)d_in[0];
    const float* Wq = (const float*)d_in[1];
    const float* Wk = (const float*)d_in[2];
    const float* Wv = (const float*)d_in[3];
    float* out = (float*)d_out;

    cudaFuncSetAttribute(proj_mma, cudaFuncAttributeMaxDynamicSharedMemorySize, PJ_SMEM);
    cudaFuncSetAttribute(attn_mma, cudaFuncAttributeMaxDynamicSharedMemorySize, AT_SMEM);

    convW<<<1536, 256>>>(Wq, Wk, Wv);
    convX<<<BT * Cn / 512, 256>>>(x);
    proj_mma<<<dim3(BT / 128, 3), 512, PJ_SMEM>>>();
    attn_mma<<<dim3(Tn / 128, Bn), 512, AT_SMEM>>>(out);
}